// round 2
// baseline (speedup 1.0000x reference)
#include <cuda_runtime.h>

// ---------------- problem constants ----------------
constexpr int P    = 10000;
constexpr int NPN  = 50;
constexpr int EPN  = 200;
constexpr int IN   = 64;
constexpr int HE   = 256;
constexpr int C2   = 64;
constexpr int RD   = 128;
constexpr int HM   = 256;
constexpr int OUTC = 16;
constexpr int EM   = 160000;
constexpr float EPSV  = 1e-5f;
constexpr float SLOPE = 0.01f;

// ---------------- device scratch ----------------
__device__ float  gEmb[P * RD];
__device__ int    gCntOut[P], gCntIn[P];
__device__ float  gRsOut[P], gRsIn[P];
__device__ float  gAgg1[P * RD];
__device__ float  gAgg2[P * HM];
__device__ float  gH[P * HM];
__device__ float  gH2[P * HM];
__device__ double gSums[2 * HM], gSums2[2 * HM], gRoSum[2 * HM];
__device__ float  gScale[2 * HM], gShift[2 * HM];

// ---------------- patch kernel smem layout (float indices) ----------------
constexpr int SF    = 0;               // feat 50x64; later h2 out 64x64
constexpr int SA    = 4096;            // h1 52x256
constexpr int SB    = SA + 52 * 256;   // gconv outputs (gc1 52x64 / gc2 64x264)
constexpr int SBSTR = 264;
constexpr int SEW   = SB + 64 * SBSTR;
constexpr int SRTW  = SEW + EPN;
constexpr int SRSO  = SRTW + EPN;
constexpr int SRSI  = SRSO + NPN;
constexpr int SR0   = SRSI + NPN;      // r0[64] r1[256] r2[64] contiguous
constexpr int SR1   = SR0 + IN;
constexpr int SR2   = SR1 + HE;
constexpr int SGA   = SR2 + C2;        // scale[256]
constexpr int SGB   = SGA + HE;        // shift[256]
constexpr int SRED  = SGB + HE;        // partials[256]
constexpr int SINT  = SRED + HE;
constexpr int NI_SSRC = 0, NI_SDST = EPN, NI_SRTS = 2 * EPN;
constexpr int NI_START = 3 * EPN;
constexpr int NI_FILL  = NI_START + NPN + 1;
constexpr int NI_CIN   = NI_FILL + NPN;
constexpr int NI_COUT  = NI_CIN + NPN;
constexpr int NINTS    = NI_COUT + NPN;
constexpr int SMEM_PATCH = (SINT + NINTS) * 4;

// =====================================================================
// Patch embedder: one CTA per patch, fused.
// =====================================================================
__global__ void __launch_bounds__(256) patch_kernel(
    const float* __restrict__ feats, const int* __restrict__ srcs,
    const int* __restrict__ dsts, const float* __restrict__ ews,
    const float* __restrict__ W1, const float* __restrict__ g1,
    const float* __restrict__ b1, const float* __restrict__ W2,
    const float* __restrict__ g2, const float* __restrict__ b2,
    const float* __restrict__ We)
{
    extern __shared__ float sm[];
    int* smi    = (int*)(sm + SINT);
    int* ssrc   = smi + NI_SSRC;
    int* sdst   = smi + NI_SDST;
    int* srts   = smi + NI_SRTS;
    int* sstart = smi + NI_START;
    int* sfill  = smi + NI_FILL;
    int* scin   = smi + NI_CIN;
    int* scout  = smi + NI_COUT;
    const int p = blockIdx.x, t = threadIdx.x;

    for (int i = t; i < EPN; i += 256) {
        ssrc[i] = srcs[p * EPN + i];
        sdst[i] = dsts[p * EPN + i];
        sm[SEW + i] = ews[p * EPN + i];
    }
    {
        const float4* f4 = (const float4*)(feats + (long long)p * NPN * IN);
        float4* s4 = (float4*)(sm + SF);
        for (int i = t; i < NPN * IN / 4; i += 256) s4[i] = f4[i];
    }
    for (int i = t; i < NPN; i += 256) { scin[i] = 0; scout[i] = 0; sfill[i] = 0; }
    __syncthreads();

    if (t < EPN) { atomicAdd(&scout[ssrc[t]], 1); atomicAdd(&scin[sdst[t]], 1); }
    __syncthreads();
    if (t < NPN) {
        sm[SRSO + t] = rsqrtf((float)(scout[t] > 0 ? scout[t] : 1));
        sm[SRSI + t] = rsqrtf((float)(scin[t]  > 0 ? scin[t]  : 1));
    }
    if (t == 0) {
        int s = 0;
        for (int n = 0; n < NPN; n++) { sstart[n] = s; s += scin[n]; }
        sstart[NPN] = s;
    }
    if (t < IN) {  // r0 = feat.mean(0)
        float s = 0.f;
        for (int n = 0; n < NPN; n++) s += sm[SF + n * IN + t];
        sm[SR0 + t] = s * (1.f / NPN);
    }
    __syncthreads();

    // counting sort by dst; fold rsqrt(deg_out[src]) into edge weight
    if (t < EPN) {
        int d = sdst[t];
        int pos = sstart[d] + atomicAdd(&sfill[d], 1);
        srts[pos] = ssrc[t];
        sm[SRTW + pos] = sm[SEW + t] * sm[SRSO + ssrc[t]];
    }
    __syncthreads();

    // gconv1 gather: sB[52 x 64], rows >=50 zero
    for (int i = t; i < 52 * IN; i += 256) {
        int n = i >> 6, c = i & 63;
        float a = 0.f;
        if (n < NPN) {
            int e1 = sstart[n + 1];
            for (int e = sstart[n]; e < e1; ++e)
                a = fmaf(sm[SF + srts[e] * IN + c], sm[SRTW + e], a);
            a *= sm[SRSI + n];
        }
        sm[SB + i] = a;
    }
    __syncthreads();

    // GEMM1: sA[52x256] = sB[52x64] @ W1[64x256]
    {
        int c0 = (t & 63) * 4, ng = t >> 6;
        float acc[13][4];
        #pragma unroll
        for (int j = 0; j < 13; j++) { acc[j][0]=0.f; acc[j][1]=0.f; acc[j][2]=0.f; acc[j][3]=0.f; }
        for (int k = 0; k < IN; k++) {
            float4 w = __ldg((const float4*)(W1 + k * HE + c0));
            #pragma unroll
            for (int j = 0; j < 13; j++) {
                float x = sm[SB + (ng + j * 4) * IN + k];
                acc[j][0] = fmaf(x, w.x, acc[j][0]);
                acc[j][1] = fmaf(x, w.y, acc[j][1]);
                acc[j][2] = fmaf(x, w.z, acc[j][2]);
                acc[j][3] = fmaf(x, w.w, acc[j][3]);
            }
        }
        #pragma unroll
        for (int j = 0; j < 13; j++)
            *(float4*)(sm + SA + (ng + j * 4) * HE + c0) =
                make_float4(acc[j][0], acc[j][1], acc[j][2], acc[j][3]);
    }
    __syncthreads();

    // graph_norm(g1,b1)
    if (t < HE) {
        float s = 0.f, s2 = 0.f;
        for (int n = 0; n < NPN; n++) { float v = sm[SA + n * HE + t]; s += v; s2 = fmaf(v, v, s2); }
        float mu = s * (1.f / NPN), var = s2 * (1.f / NPN) - mu * mu;
        float sc = g1[t] * rsqrtf(var + EPSV);
        sm[SGA + t] = sc; sm[SGB + t] = b1[t] - mu * sc;
    }
    __syncthreads();
    for (int i = t; i < NPN * HE; i += 256) {
        int c = i & 255;
        float v = fmaf(sm[SA + i], sm[SGA + c], sm[SGB + c]);
        sm[SA + i] = v >= 0.f ? v : SLOPE * v;
    }
    __syncthreads();
    if (t < HE) {  // r1
        float s = 0.f;
        for (int n = 0; n < NPN; n++) s += sm[SA + n * HE + t];
        sm[SR1 + t] = s * (1.f / NPN);
    }

    // gconv2 gather: sB[64 x 264], rows >=50 zero
    for (int i = t; i < 64 * HE; i += 256) {
        int n = i >> 8, c = i & 255;
        float a = 0.f;
        if (n < NPN) {
            int e1 = sstart[n + 1];
            for (int e = sstart[n]; e < e1; ++e)
                a = fmaf(sm[SA + srts[e] * HE + c], sm[SRTW + e], a);
            a *= sm[SRSI + n];
        }
        sm[SB + n * SBSTR + c] = a;
    }
    __syncthreads();

    // GEMM2: sF[64x64] = sB[64x256] @ W2[256x64]
    {
        int c0 = (t & 15) * 4, ng = t >> 4;
        float acc[4][4];
        #pragma unroll
        for (int j = 0; j < 4; j++) { acc[j][0]=0.f; acc[j][1]=0.f; acc[j][2]=0.f; acc[j][3]=0.f; }
        for (int k = 0; k < HE; k++) {
            float4 w = __ldg((const float4*)(W2 + k * C2 + c0));
            #pragma unroll
            for (int j = 0; j < 4; j++) {
                float x = sm[SB + (ng + j * 16) * SBSTR + k];
                acc[j][0] = fmaf(x, w.x, acc[j][0]);
                acc[j][1] = fmaf(x, w.y, acc[j][1]);
                acc[j][2] = fmaf(x, w.z, acc[j][2]);
                acc[j][3] = fmaf(x, w.w, acc[j][3]);
            }
        }
        #pragma unroll
        for (int j = 0; j < 4; j++)
            *(float4*)(sm + SF + (ng + j * 16) * C2 + c0) =
                make_float4(acc[j][0], acc[j][1], acc[j][2], acc[j][3]);
    }
    __syncthreads();

    // graph_norm(g2,b2)
    if (t < C2) {
        float s = 0.f, s2 = 0.f;
        for (int n = 0; n < NPN; n++) { float v = sm[SF + n * C2 + t]; s += v; s2 = fmaf(v, v, s2); }
        float mu = s * (1.f / NPN), var = s2 * (1.f / NPN) - mu * mu;
        float sc = g2[t] * rsqrtf(var + EPSV);
        sm[SGA + t] = sc; sm[SGB + t] = b2[t] - mu * sc;
    }
    __syncthreads();
    for (int i = t; i < NPN * C2; i += 256) {
        int c = i & 63;
        float v = fmaf(sm[SF + i], sm[SGA + c], sm[SGB + c]);
        sm[SF + i] = v >= 0.f ? v : SLOPE * v;
    }
    __syncthreads();
    if (t < C2) {  // r2
        float s = 0.f;
        for (int n = 0; n < NPN; n++) s += sm[SF + n * C2 + t];
        sm[SR2 + t] = s * (1.f / NPN);
    }
    __syncthreads();

    // emb = concat(r0,r1,r2)[384] @ We[384x128]
    {
        int j = t & 127, hf = t >> 7;
        float a = 0.f;
        int k0 = hf * 192;
        for (int k = k0; k < k0 + 192; k++)
            a = fmaf(sm[SR0 + k], __ldg(&We[k * RD + j]), a);
        sm[SRED + t] = a;
    }
    __syncthreads();
    float e = 0.f;
    if (t < RD) { e = sm[SRED + t] + sm[SRED + t + 128]; sm[SGB + t] = e; }
    __syncthreads();
    if (t == 0) {  // instance norm stats over 128 channels
        float s = 0.f, s2 = 0.f;
        for (int i = 0; i < RD; i++) { float v = sm[SGB + i]; s += v; s2 = fmaf(v, v, s2); }
        float mu = s * (1.f / RD), var = s2 * (1.f / RD) - mu * mu;
        sm[SGA] = mu; sm[SGA + 1] = rsqrtf(var + EPSV);
    }
    __syncthreads();
    if (t < RD) {
        float y = (e - sm[SGA]) * sm[SGA + 1];
        y = y >= 0.f ? y : SLOPE * y;
        gEmb[p * RD + t] = y;
    }
}

// =====================================================================
// Mesh stage kernels
// =====================================================================
__global__ void init_zero() {
    int i = blockIdx.x * 256 + threadIdx.x;
    if (i < P * HM) gAgg2[i] = 0.f;
    if (i < P * RD) gAgg1[i] = 0.f;
    if (i < P) { gCntOut[i] = 0; gCntIn[i] = 0; }
    if (i < 2 * HM) { gSums[i] = 0.0; gSums2[i] = 0.0; gRoSum[i] = 0.0; }
}

__global__ void mesh_deg(const int* __restrict__ src, const int* __restrict__ dst) {
    int e = blockIdx.x * 256 + threadIdx.x;
    if (e < EM) { atomicAdd(&gCntOut[src[e]], 1); atomicAdd(&gCntIn[dst[e]], 1); }
}

__global__ void mesh_rs() {
    int i = blockIdx.x * 256 + threadIdx.x;
    if (i < P) {
        gRsOut[i] = rsqrtf((float)(gCntOut[i] > 0 ? gCntOut[i] : 1));
        gRsIn[i]  = rsqrtf((float)(gCntIn[i]  > 0 ? gCntIn[i]  : 1));
    }
}

// scatter: Y[dst, :] += X[src, :] * ew * rsOut[src];  C = 1<<cshift channels/4
__global__ void mesh_scatter(const float* __restrict__ X, float* __restrict__ Y,
                             const int* __restrict__ src, const int* __restrict__ dst,
                             const float* __restrict__ ew, int cshift) {
    long long tid = (long long)blockIdx.x * 256 + threadIdx.x;
    int cg = 1 << cshift;                    // channel groups (C/4)
    if (tid >= (long long)EM * cg) return;
    int e  = (int)(tid >> cshift);
    int c0 = ((int)tid & (cg - 1)) * 4;
    int C  = cg * 4;
    int s = src[e], d = dst[e];
    float w = ew[e] * gRsOut[s];
    float4 x = *(const float4*)(X + (long long)s * C + c0);
    float* y = Y + (long long)d * C + c0;
    atomicAdd(y + 0, x.x * w);
    atomicAdd(y + 1, x.y * w);
    atomicAdd(y + 2, x.z * w);
    atomicAdd(y + 3, x.w * w);
}

// Y[P x 256] = (X[P x K] * rsIn[row]) @ W[K x 256]
template <int K>
__global__ void __launch_bounds__(256) mesh_gemm(const float* __restrict__ X,
                                                 const float* __restrict__ W,
                                                 float* __restrict__ Y) {
    __shared__ float xs[16 * K];
    int r0 = blockIdx.x * 16;
    int t = threadIdx.x;
    for (int i = t; i < 16 * K; i += 256) {
        int r = i / K, k = i - r * K;
        xs[r * K + k] = X[(long long)(r0 + r) * K + k] * gRsIn[r0 + r];
    }
    __syncthreads();
    int c0 = (t & 63) * 4, tr = t >> 6;
    float acc[4][4];
    #pragma unroll
    for (int j = 0; j < 4; j++) { acc[j][0]=0.f; acc[j][1]=0.f; acc[j][2]=0.f; acc[j][3]=0.f; }
    for (int k = 0; k < K; k++) {
        float4 w = __ldg((const float4*)(W + k * HM + c0));
        #pragma unroll
        for (int j = 0; j < 4; j++) {
            float x = xs[(tr + 4 * j) * K + k];
            acc[j][0] = fmaf(x, w.x, acc[j][0]);
            acc[j][1] = fmaf(x, w.y, acc[j][1]);
            acc[j][2] = fmaf(x, w.z, acc[j][2]);
            acc[j][3] = fmaf(x, w.w, acc[j][3]);
        }
    }
    #pragma unroll
    for (int j = 0; j < 4; j++)
        *(float4*)(Y + (long long)(r0 + tr + 4 * j) * HM + c0) =
            make_float4(acc[j][0], acc[j][1], acc[j][2], acc[j][3]);
}

// per-channel sum / sumsq over P rows (200 blocks x 50 rows)
__global__ void mesh_stats(const float* __restrict__ Y, int off) {
    int c = threadIdx.x;
    int r0 = blockIdx.x * 50;
    float s = 0.f, s2 = 0.f;
    for (int i = 0; i < 50; i++) {
        float v = Y[(long long)(r0 + i) * HM + c];
        s += v; s2 = fmaf(v, v, s2);
    }
    atomicAdd(&gSums[off + c], (double)s);
    atomicAdd(&gSums2[off + c], (double)s2);
}

__global__ void mesh_finalize(const float* __restrict__ g, const float* __restrict__ b, int off) {
    int c = threadIdx.x;
    double mu = gSums[off + c] / P;
    double var = gSums2[off + c] / P - mu * mu;
    float sc = g[c] * rsqrtf((float)var + EPSV);
    gScale[off + c] = sc;
    gShift[off + c] = b[c] - (float)mu * sc;
}

// apply affine norm + lrelu, accumulate readout sums
__global__ void mesh_apply(float* __restrict__ Y, int off) {
    int c = threadIdx.x;
    int r0 = blockIdx.x * 50;
    float sc = gScale[off + c], sh = gShift[off + c];
    float s = 0.f;
    for (int i = 0; i < 50; i++) {
        long long idx = (long long)(r0 + i) * HM + c;
        float v = fmaf(Y[idx], sc, sh);
        v = v >= 0.f ? v : SLOPE * v;
        Y[idx] = v;
        s += v;
    }
    atomicAdd(&gRoSum[off + c], (double)s);
}

__global__ void final_kernel(const float* __restrict__ Wcls, float* __restrict__ out) {
    int t = threadIdx.x;
    if (t < OUTC) {
        float a = 0.f;
        for (int k = 0; k < 2 * HM; k++)
            a = fmaf((float)(gRoSum[k] / P), __ldg(&Wcls[k * OUTC + t]), a);
        out[t] = a;
    }
}

// =====================================================================
extern "C" void kernel_launch(void* const* d_in, const int* in_sizes, int n_in,
                              void* d_out, int out_size) {
    const float* patch_feats = (const float*)d_in[0];
    const int*   patch_src   = (const int*)d_in[1];
    const int*   patch_dst   = (const int*)d_in[2];
    const float* patch_ew    = (const float*)d_in[3];
    const int*   mesh_src    = (const int*)d_in[4];
    const int*   mesh_dst    = (const int*)d_in[5];
    const float* mesh_ew     = (const float*)d_in[6];
    const float* W1  = (const float*)d_in[7];
    const float* g1  = (const float*)d_in[8];
    const float* b1  = (const float*)d_in[9];
    const float* W2  = (const float*)d_in[10];
    const float* g2  = (const float*)d_in[11];
    const float* b2  = (const float*)d_in[12];
    const float* We  = (const float*)d_in[13];
    const float* Wc1 = (const float*)d_in[14];
    const float* g3  = (const float*)d_in[15];
    const float* b3  = (const float*)d_in[16];
    const float* Wc2 = (const float*)d_in[17];
    const float* g4  = (const float*)d_in[18];
    const float* b4  = (const float*)d_in[19];
    const float* Wcls = (const float*)d_in[20];
    float* out = (float*)d_out;

    cudaFuncSetAttribute(patch_kernel, cudaFuncAttributeMaxDynamicSharedMemorySize, SMEM_PATCH);

    // resolve device-global symbol addresses (host API, not captured)
    void *pEmb, *pAgg1, *pAgg2, *pH, *pH2;
    cudaGetSymbolAddress(&pEmb,  gEmb);
    cudaGetSymbolAddress(&pAgg1, gAgg1);
    cudaGetSymbolAddress(&pAgg2, gAgg2);
    cudaGetSymbolAddress(&pH,    gH);
    cudaGetSymbolAddress(&pH2,   gH2);

    init_zero<<<(P * HM + 255) / 256, 256>>>();
    patch_kernel<<<P, 256, SMEM_PATCH>>>(patch_feats, patch_src, patch_dst, patch_ew,
                                         W1, g1, b1, W2, g2, b2, We);
    mesh_deg<<<(EM + 255) / 256, 256>>>(mesh_src, mesh_dst);
    mesh_rs<<<(P + 255) / 256, 256>>>();

    // conv1: scatter emb (C=128 -> cshift=5), gemm vs Wc1
    mesh_scatter<<<(EM * (RD / 4) + 255) / 256, 256>>>((const float*)pEmb, (float*)pAgg1,
                                                       mesh_src, mesh_dst, mesh_ew, 5);
    mesh_gemm<RD><<<P / 16, 256>>>((const float*)pAgg1, Wc1, (float*)pH);
    mesh_stats<<<P / 50, 256>>>((const float*)pH, 0);
    mesh_finalize<<<1, 256>>>(g3, b3, 0);
    mesh_apply<<<P / 50, 256>>>((float*)pH, 0);

    // conv2: scatter h (C=256 -> cshift=6), gemm vs Wc2
    mesh_scatter<<<(EM * (HM / 4) + 255) / 256, 256>>>((const float*)pH, (float*)pAgg2,
                                                       mesh_src, mesh_dst, mesh_ew, 6);
    mesh_gemm<HM><<<P / 16, 256>>>((const float*)pAgg2, Wc2, (float*)pH2);
    mesh_stats<<<P / 50, 256>>>((const float*)pH2, HM);
    mesh_finalize<<<1, 256>>>(g4, b4, HM);
    mesh_apply<<<P / 50, 256>>>((float*)pH2, HM);

    final_kernel<<<1, 32>>>(Wcls, out);
}

// round 3
// speedup vs baseline: 1.8163x; 1.8163x over previous
#include <cuda_runtime.h>

// ---------------- problem constants ----------------
constexpr int P    = 10000;
constexpr int NPN  = 50;
constexpr int EPN  = 200;
constexpr int IN   = 64;
constexpr int HE   = 256;
constexpr int C2   = 64;
constexpr int RD   = 128;
constexpr int HM   = 256;
constexpr int OUTC = 16;
constexpr int EM   = 160000;
constexpr float EPSV  = 1e-5f;
constexpr float SLOPE = 0.01f;

// ---------------- device scratch ----------------
__device__ float  gEmb[P * RD];
__device__ int    gCntOut[P], gCntIn[P], gFill[P];
__device__ int    gOffs[P + 1];
__device__ float  gRsOut[P], gRsIn[P];
__device__ int    gSrtSrc[EM];
__device__ float  gSrtW[EM];
__device__ float  gAgg1[P * RD];
__device__ float  gAgg2[P * HM];
__device__ float  gH[P * HM];
__device__ float  gH2[P * HM];
__device__ double gSums[2 * HM], gSums2[2 * HM], gRoSum[2 * HM];
__device__ float  gScale[2 * HM], gShift[2 * HM];

// ---------------- patch kernel smem layout (float indices) ----------------
constexpr int H1S  = 264;              // padded h1 row stride
constexpr int SH1  = 0;                // h1 [64 x 264] (rows 52..63 zeroed)
constexpr int ST   = 64 * H1S;         // t1 [52x64] then t2 [64x64]
constexpr int SFT  = ST + 64 * 64;     // feat [50x64] then u [52x64]
constexpr int SEW  = SFT + 3328;       // raw edge weights [200]
constexpr int SRTW = SEW + EPN;        // sorted weights [200]
constexpr int SRSO = SRTW + EPN;       // rsqrt deg_out [50]
constexpr int SRSI = SRSO + NPN;       // rsqrt deg_in  [50]
constexpr int SR0  = SRSI + NPN;       // r0[64] r1[256] r2[64] contiguous
constexpr int SR1  = SR0 + IN;
constexpr int SR2  = SR1 + HE;
constexpr int SGA  = SR2 + C2;         // scale [256]
constexpr int SGB  = SGA + HE;         // shift [256]
constexpr int SRED = SGB + HE;         // partials [256]
constexpr int SINT = SRED + HE;
constexpr int NI_SSRC = 0, NI_SDST = EPN, NI_SRTS = 2 * EPN;
constexpr int NI_START = 3 * EPN;      // [51]
constexpr int NI_FILL  = NI_START + NPN + 1;
constexpr int NI_CIN   = NI_FILL + NPN;
constexpr int NI_COUT  = NI_CIN + NPN;
constexpr int NINTS    = NI_COUT + NPN;
constexpr int SMEM_PATCH = (SINT + NINTS) * 4;   // ~107 KB -> 2 CTAs/SM

// =====================================================================
// Patch embedder: one CTA per patch, fused; conv2/GEMM2 order swapped
// (graph_conv(h) @ W2 == graph_conv(h @ W2), both linear).
// =====================================================================
__global__ void __launch_bounds__(256, 2) patch_kernel(
    const float* __restrict__ feats, const int* __restrict__ srcs,
    const int* __restrict__ dsts, const float* __restrict__ ews,
    const float* __restrict__ W1, const float* __restrict__ g1,
    const float* __restrict__ b1, const float* __restrict__ W2,
    const float* __restrict__ g2, const float* __restrict__ b2,
    const float* __restrict__ We)
{
    extern __shared__ float sm[];
    int* smi    = (int*)(sm + SINT);
    int* ssrc   = smi + NI_SSRC;
    int* sdst   = smi + NI_SDST;
    int* srts   = smi + NI_SRTS;
    int* sstart = smi + NI_START;
    int* sfill  = smi + NI_FILL;
    int* scin   = smi + NI_CIN;
    int* scout  = smi + NI_COUT;
    const int p = blockIdx.x, t = threadIdx.x;

    for (int i = t; i < EPN; i += 256) {
        ssrc[i] = srcs[p * EPN + i];
        sdst[i] = dsts[p * EPN + i];
        sm[SEW + i] = ews[p * EPN + i];
    }
    {
        const float4* f4 = (const float4*)(feats + (long long)p * NPN * IN);
        float4* s4 = (float4*)(sm + SFT);
        for (int i = t; i < NPN * IN / 4; i += 256) s4[i] = f4[i];
    }
    for (int i = t; i < NPN; i += 256) { scin[i] = 0; scout[i] = 0; sfill[i] = 0; }
    // zero h1 rows 52..63 (read by GEMM2's 64-row tiling)
    for (int i = t; i < 12 * H1S; i += 256) sm[SH1 + 52 * H1S + i] = 0.f;
    __syncthreads();

    if (t < EPN) { atomicAdd(&scout[ssrc[t]], 1); atomicAdd(&scin[sdst[t]], 1); }
    __syncthreads();
    if (t < NPN) {
        sm[SRSO + t] = rsqrtf((float)(scout[t] > 0 ? scout[t] : 1));
        sm[SRSI + t] = rsqrtf((float)(scin[t]  > 0 ? scin[t]  : 1));
    }
    if (t == 0) {
        int s = 0;
        for (int n = 0; n < NPN; n++) { sstart[n] = s; s += scin[n]; }
        sstart[NPN] = s;
    }
    if (t < IN) {  // r0 = feat.mean(0)
        float s = 0.f;
        for (int n = 0; n < NPN; n++) s += sm[SFT + n * IN + t];
        sm[SR0 + t] = s * (1.f / NPN);
    }
    __syncthreads();

    // counting sort by dst; fold rsqrt(deg_out[src]) into edge weight
    if (t < EPN) {
        int d = sdst[t];
        int pos = sstart[d] + atomicAdd(&sfill[d], 1);
        srts[pos] = ssrc[t];
        sm[SRTW + pos] = sm[SEW + t] * sm[SRSO + ssrc[t]];
    }
    __syncthreads();

    // gconv1 gather: t1[52 x 64] (rows >= 50 zero)
    for (int i = t; i < 52 * IN; i += 256) {
        int n = i >> 6, c = i & 63;
        float a = 0.f;
        if (n < NPN) {
            int e1 = sstart[n + 1];
            for (int e = sstart[n]; e < e1; ++e)
                a = fmaf(sm[SFT + srts[e] * IN + c], sm[SRTW + e], a);
            a *= sm[SRSI + n];
        }
        sm[ST + i] = a;
    }
    __syncthreads();

    // GEMM1: h1[52 x 256(pad 264)] = t1[52x64] @ W1[64x256]
    {
        int c0 = (t & 63) * 4, ng = t >> 6;
        float acc[13][4];
        #pragma unroll
        for (int j = 0; j < 13; j++) { acc[j][0]=0.f; acc[j][1]=0.f; acc[j][2]=0.f; acc[j][3]=0.f; }
        for (int k = 0; k < IN; k++) {
            float4 w = __ldg((const float4*)(W1 + k * HE + c0));
            #pragma unroll
            for (int j = 0; j < 13; j++) {
                float x = sm[ST + (ng + j * 4) * IN + k];
                acc[j][0] = fmaf(x, w.x, acc[j][0]);
                acc[j][1] = fmaf(x, w.y, acc[j][1]);
                acc[j][2] = fmaf(x, w.z, acc[j][2]);
                acc[j][3] = fmaf(x, w.w, acc[j][3]);
            }
        }
        #pragma unroll
        for (int j = 0; j < 13; j++)
            *(float4*)(sm + SH1 + (ng + j * 4) * H1S + c0) =
                make_float4(acc[j][0], acc[j][1], acc[j][2], acc[j][3]);
    }
    __syncthreads();

    // graph_norm(g1,b1) + lrelu (rows < 50 only; rows 50..63 stay zero)
    if (t < HE) {
        float s = 0.f, s2 = 0.f;
        for (int n = 0; n < NPN; n++) { float v = sm[SH1 + n * H1S + t]; s += v; s2 = fmaf(v, v, s2); }
        float mu = s * (1.f / NPN), var = s2 * (1.f / NPN) - mu * mu;
        float sc = g1[t] * rsqrtf(var + EPSV);
        sm[SGA + t] = sc; sm[SGB + t] = b1[t] - mu * sc;
    }
    __syncthreads();
    for (int i = t; i < NPN * HE; i += 256) {
        int n = i >> 8, c = i & 255;
        float v = fmaf(sm[SH1 + n * H1S + c], sm[SGA + c], sm[SGB + c]);
        sm[SH1 + n * H1S + c] = v >= 0.f ? v : SLOPE * v;
    }
    __syncthreads();
    if (t < HE) {  // r1
        float s = 0.f;
        for (int n = 0; n < NPN; n++) s += sm[SH1 + n * H1S + t];
        sm[SR1 + t] = s * (1.f / NPN);
    }
    __syncthreads();

    // GEMM2: t2[64x64] = h1[64x264] @ W2[256x64]  (rows 52..63 of h1 are zero)
    {
        int c0 = (t & 15) * 4, rg = t >> 4;
        float acc[4][4];
        #pragma unroll
        for (int j = 0; j < 4; j++) { acc[j][0]=0.f; acc[j][1]=0.f; acc[j][2]=0.f; acc[j][3]=0.f; }
        for (int k = 0; k < HE; k++) {
            float4 w = __ldg((const float4*)(W2 + k * C2 + c0));
            #pragma unroll
            for (int j = 0; j < 4; j++) {
                float x = sm[SH1 + (rg + 16 * j) * H1S + k];
                acc[j][0] = fmaf(x, w.x, acc[j][0]);
                acc[j][1] = fmaf(x, w.y, acc[j][1]);
                acc[j][2] = fmaf(x, w.z, acc[j][2]);
                acc[j][3] = fmaf(x, w.w, acc[j][3]);
            }
        }
        #pragma unroll
        for (int j = 0; j < 4; j++)
            *(float4*)(sm + ST + (rg + 16 * j) * C2 + c0) =
                make_float4(acc[j][0], acc[j][1], acc[j][2], acc[j][3]);
    }
    __syncthreads();

    // gconv2 gather on 64 channels: u[52x64] at SFT (feat is dead)
    for (int i = t; i < 52 * C2; i += 256) {
        int n = i >> 6, c = i & 63;
        float a = 0.f;
        if (n < NPN) {
            int e1 = sstart[n + 1];
            for (int e = sstart[n]; e < e1; ++e)
                a = fmaf(sm[ST + srts[e] * C2 + c], sm[SRTW + e], a);
            a *= sm[SRSI + n];
        }
        sm[SFT + i] = a;
    }
    __syncthreads();

    // graph_norm(g2,b2) + lrelu on u
    if (t < C2) {
        float s = 0.f, s2 = 0.f;
        for (int n = 0; n < NPN; n++) { float v = sm[SFT + n * C2 + t]; s += v; s2 = fmaf(v, v, s2); }
        float mu = s * (1.f / NPN), var = s2 * (1.f / NPN) - mu * mu;
        float sc = g2[t] * rsqrtf(var + EPSV);
        sm[SGA + t] = sc; sm[SGB + t] = b2[t] - mu * sc;
    }
    __syncthreads();
    for (int i = t; i < NPN * C2; i += 256) {
        int c = i & 63;
        float v = fmaf(sm[SFT + i], sm[SGA + c], sm[SGB + c]);
        sm[SFT + i] = v >= 0.f ? v : SLOPE * v;
    }
    __syncthreads();
    if (t < C2) {  // r2
        float s = 0.f;
        for (int n = 0; n < NPN; n++) s += sm[SFT + n * C2 + t];
        sm[SR2 + t] = s * (1.f / NPN);
    }
    __syncthreads();

    // emb = concat(r0,r1,r2)[384] @ We[384x128]
    {
        int j = t & 127, hf = t >> 7;
        float a = 0.f;
        int k0 = hf * 192;
        for (int k = k0; k < k0 + 192; k++)
            a = fmaf(sm[SR0 + k], __ldg(&We[k * RD + j]), a);
        sm[SRED + t] = a;
    }
    __syncthreads();
    float e = 0.f;
    if (t < RD) { e = sm[SRED + t] + sm[SRED + t + 128]; sm[SGB + t] = e; }
    __syncthreads();
    if (t == 0) {  // instance-norm stats over 128 channels
        float s = 0.f, s2 = 0.f;
        for (int i = 0; i < RD; i++) { float v = sm[SGB + i]; s += v; s2 = fmaf(v, v, s2); }
        float mu = s * (1.f / RD), var = s2 * (1.f / RD) - mu * mu;
        sm[SGA] = mu; sm[SGA + 1] = rsqrtf(var + EPSV);
    }
    __syncthreads();
    if (t < RD) {
        float y = (e - sm[SGA]) * sm[SGA + 1];
        y = y >= 0.f ? y : SLOPE * y;
        gEmb[p * RD + t] = y;
    }
}

// =====================================================================
// Mesh stage: CSR gather (no float atomics, no zero-fill of aggregates)
// =====================================================================
__global__ void init_zero() {
    int i = blockIdx.x * 256 + threadIdx.x;
    if (i < P) { gCntOut[i] = 0; gCntIn[i] = 0; gFill[i] = 0; }
    if (i < 2 * HM) { gSums[i] = 0.0; gSums2[i] = 0.0; gRoSum[i] = 0.0; }
}

__global__ void mesh_deg(const int* __restrict__ src, const int* __restrict__ dst) {
    int e = blockIdx.x * 256 + threadIdx.x;
    if (e < EM) { atomicAdd(&gCntOut[src[e]], 1); atomicAdd(&gCntIn[dst[e]], 1); }
}

__global__ void mesh_rs() {
    int i = blockIdx.x * 256 + threadIdx.x;
    if (i < P) {
        gRsOut[i] = rsqrtf((float)(gCntOut[i] > 0 ? gCntOut[i] : 1));
        gRsIn[i]  = rsqrtf((float)(gCntIn[i]  > 0 ? gCntIn[i]  : 1));
    }
}

__global__ void mesh_scan() {  // single block: exclusive scan of in-degrees
    __shared__ int part[256];
    int t = threadIdx.x;
    const int CH = (P + 255) / 256;
    int base = t * CH, s = 0;
    for (int i = 0; i < CH; i++) { int idx = base + i; if (idx < P) s += gCntIn[idx]; }
    part[t] = s; __syncthreads();
    for (int off = 1; off < 256; off <<= 1) {
        int v = (t >= off) ? part[t - off] : 0;
        __syncthreads();
        part[t] += v;
        __syncthreads();
    }
    int run = (t == 0) ? 0 : part[t - 1];
    for (int i = 0; i < CH; i++) {
        int idx = base + i;
        if (idx < P) { gOffs[idx] = run; run += gCntIn[idx]; }
    }
    if (t == 255) gOffs[P] = run;
}

__global__ void mesh_sort(const int* __restrict__ src, const int* __restrict__ dst,
                          const float* __restrict__ ew) {
    int e = blockIdx.x * 256 + threadIdx.x;
    if (e < EM) {
        int d = dst[e], s = src[e];
        int pos = gOffs[d] + atomicAdd(&gFill[d], 1);
        gSrtSrc[pos] = s;
        gSrtW[pos] = ew[e] * gRsOut[s];
    }
}

// gather, C=128: 2 nodes per block
__global__ void mesh_gather128(const float* __restrict__ X, float* __restrict__ Y) {
    int n = blockIdx.x * 2 + (threadIdx.x >> 7);
    int c = threadIdx.x & 127;
    int e1 = gOffs[n + 1];
    float a = 0.f;
    for (int e = gOffs[n]; e < e1; ++e)
        a = fmaf(__ldg(&X[(long long)gSrtSrc[e] * 128 + c]), gSrtW[e], a);
    Y[(long long)n * 128 + c] = a * gRsIn[n];
}

// gather, C=256: 1 node per block
__global__ void mesh_gather256(const float* __restrict__ X, float* __restrict__ Y) {
    int n = blockIdx.x;
    int c = threadIdx.x;
    int e1 = gOffs[n + 1];
    float a = 0.f;
    for (int e = gOffs[n]; e < e1; ++e)
        a = fmaf(__ldg(&X[(long long)gSrtSrc[e] * 256 + c]), gSrtW[e], a);
    Y[(long long)n * 256 + c] = a * gRsIn[n];
}

// Y[P x 256] = X[P x K] @ W[K x 256]
template <int K>
__global__ void __launch_bounds__(256) mesh_gemm(const float* __restrict__ X,
                                                 const float* __restrict__ W,
                                                 float* __restrict__ Y) {
    __shared__ float xs[16 * K];
    int r0 = blockIdx.x * 16;
    int t = threadIdx.x;
    for (int i = t; i < 16 * K; i += 256)
        xs[i] = X[(long long)r0 * K + i];
    __syncthreads();
    int c0 = (t & 63) * 4, tr = t >> 6;
    float acc[4][4];
    #pragma unroll
    for (int j = 0; j < 4; j++) { acc[j][0]=0.f; acc[j][1]=0.f; acc[j][2]=0.f; acc[j][3]=0.f; }
    for (int k = 0; k < K; k++) {
        float4 w = __ldg((const float4*)(W + k * HM + c0));
        #pragma unroll
        for (int j = 0; j < 4; j++) {
            float x = xs[(tr + 4 * j) * K + k];
            acc[j][0] = fmaf(x, w.x, acc[j][0]);
            acc[j][1] = fmaf(x, w.y, acc[j][1]);
            acc[j][2] = fmaf(x, w.z, acc[j][2]);
            acc[j][3] = fmaf(x, w.w, acc[j][3]);
        }
    }
    #pragma unroll
    for (int j = 0; j < 4; j++)
        *(float4*)(Y + (long long)(r0 + tr + 4 * j) * HM + c0) =
            make_float4(acc[j][0], acc[j][1], acc[j][2], acc[j][3]);
}

__global__ void mesh_stats(const float* __restrict__ Y, int off) {
    int c = threadIdx.x;
    int r0 = blockIdx.x * 50;
    float s = 0.f, s2 = 0.f;
    for (int i = 0; i < 50; i++) {
        float v = Y[(long long)(r0 + i) * HM + c];
        s += v; s2 = fmaf(v, v, s2);
    }
    atomicAdd(&gSums[off + c], (double)s);
    atomicAdd(&gSums2[off + c], (double)s2);
}

__global__ void mesh_finalize(const float* __restrict__ g, const float* __restrict__ b, int off) {
    int c = threadIdx.x;
    double mu = gSums[off + c] / P;
    double var = gSums2[off + c] / P - mu * mu;
    float sc = g[c] * rsqrtf((float)var + EPSV);
    gScale[off + c] = sc;
    gShift[off + c] = b[c] - (float)mu * sc;
}

__global__ void mesh_apply(float* __restrict__ Y, int off) {
    int c = threadIdx.x;
    int r0 = blockIdx.x * 50;
    float sc = gScale[off + c], sh = gShift[off + c];
    float s = 0.f;
    for (int i = 0; i < 50; i++) {
        long long idx = (long long)(r0 + i) * HM + c;
        float v = fmaf(Y[idx], sc, sh);
        v = v >= 0.f ? v : SLOPE * v;
        Y[idx] = v;
        s += v;
    }
    atomicAdd(&gRoSum[off + c], (double)s);
}

__global__ void final_kernel(const float* __restrict__ Wcls, float* __restrict__ out) {
    int t = threadIdx.x;
    if (t < OUTC) {
        float a = 0.f;
        for (int k = 0; k < 2 * HM; k++)
            a = fmaf((float)(gRoSum[k] / P), __ldg(&Wcls[k * OUTC + t]), a);
        out[t] = a;
    }
}

// =====================================================================
extern "C" void kernel_launch(void* const* d_in, const int* in_sizes, int n_in,
                              void* d_out, int out_size) {
    const float* patch_feats = (const float*)d_in[0];
    const int*   patch_src   = (const int*)d_in[1];
    const int*   patch_dst   = (const int*)d_in[2];
    const float* patch_ew    = (const float*)d_in[3];
    const int*   mesh_src    = (const int*)d_in[4];
    const int*   mesh_dst    = (const int*)d_in[5];
    const float* mesh_ew     = (const float*)d_in[6];
    const float* W1  = (const float*)d_in[7];
    const float* g1  = (const float*)d_in[8];
    const float* b1  = (const float*)d_in[9];
    const float* W2  = (const float*)d_in[10];
    const float* g2  = (const float*)d_in[11];
    const float* b2  = (const float*)d_in[12];
    const float* We  = (const float*)d_in[13];
    const float* Wc1 = (const float*)d_in[14];
    const float* g3  = (const float*)d_in[15];
    const float* b3  = (const float*)d_in[16];
    const float* Wc2 = (const float*)d_in[17];
    const float* g4  = (const float*)d_in[18];
    const float* b4  = (const float*)d_in[19];
    const float* Wcls = (const float*)d_in[20];
    float* out = (float*)d_out;

    cudaFuncSetAttribute(patch_kernel, cudaFuncAttributeMaxDynamicSharedMemorySize, SMEM_PATCH);

    void *pEmb, *pAgg1, *pAgg2, *pH, *pH2;
    cudaGetSymbolAddress(&pEmb,  gEmb);
    cudaGetSymbolAddress(&pAgg1, gAgg1);
    cudaGetSymbolAddress(&pAgg2, gAgg2);
    cudaGetSymbolAddress(&pH,    gH);
    cudaGetSymbolAddress(&pH2,   gH2);

    // mesh-prep first (independent of patch stage) so patch_kernel is the
    // 6th launch -> captured by ncu (-s 5 -c 1)
    init_zero<<<(P + 255) / 256, 256>>>();
    mesh_deg<<<(EM + 255) / 256, 256>>>(mesh_src, mesh_dst);
    mesh_rs<<<(P + 255) / 256, 256>>>();
    mesh_scan<<<1, 256>>>();
    mesh_sort<<<(EM + 255) / 256, 256>>>(mesh_src, mesh_dst, mesh_ew);

    patch_kernel<<<P, 256, SMEM_PATCH>>>(patch_feats, patch_src, patch_dst, patch_ew,
                                         W1, g1, b1, W2, g2, b2, We);

    // mesh conv1
    mesh_gather128<<<P / 2, 256>>>((const float*)pEmb, (float*)pAgg1);
    mesh_gemm<RD><<<P / 16, 256>>>((const float*)pAgg1, Wc1, (float*)pH);
    mesh_stats<<<P / 50, 256>>>((const float*)pH, 0);
    mesh_finalize<<<1, 256>>>(g3, b3, 0);
    mesh_apply<<<P / 50, 256>>>((float*)pH, 0);

    // mesh conv2
    mesh_gather256<<<P, 256>>>((const float*)pH, (float*)pAgg2);
    mesh_gemm<HM><<<P / 16, 256>>>((const float*)pAgg2, Wc2, (float*)pH2);
    mesh_stats<<<P / 50, 256>>>((const float*)pH2, HM);
    mesh_finalize<<<1, 256>>>(g4, b4, HM);
    mesh_apply<<<P / 50, 256>>>((float*)pH2, HM);

    final_kernel<<<1, 32>>>(Wcls, out);
}

// round 5
// speedup vs baseline: 2.2205x; 1.2225x over previous
#include <cuda_runtime.h>

// ---------------- problem constants ----------------
constexpr int P    = 10000;
constexpr int NPN  = 50;
constexpr int EPN  = 200;
constexpr int IN   = 64;
constexpr int HE   = 256;
constexpr int C2   = 64;
constexpr int RD   = 128;
constexpr int HM   = 256;
constexpr int OUTC = 16;
constexpr int EM   = 160000;
constexpr float EPSV  = 1e-5f;
constexpr float SLOPE = 0.01f;

// ---------------- packed fp32x2 helpers (sm_103a) ----------------
typedef unsigned long long u64;
#define FMA2(d, a, b, c) asm("fma.rn.f32x2 %0, %1, %2, %3;" : "=l"(d) : "l"(a), "l"(b), "l"(c))
#define MUL2(d, a, b)    asm("mul.rn.f32x2 %0, %1, %2;"     : "=l"(d) : "l"(a), "l"(b))
#define DUP2(d, x)       asm("mov.b64 %0, {%1, %1};"        : "=l"(d) : "r"(__float_as_uint(x)))

// ---------------- device scratch ----------------
__device__ float  gEmb[P * RD];
__device__ int    gCntOut[P], gCntIn[P], gFill[P];
__device__ int    gOffs[P + 1];
__device__ float  gRsOut[P], gRsIn[P];
__device__ int    gSrtSrc[EM];
__device__ float  gSrtW[EM];
__device__ float  gAgg1[P * RD];
__device__ float  gAgg2[P * HM];
__device__ float  gH[P * HM];
__device__ float  gH2[P * HM];
__device__ double gSums[2 * HM], gSums2[2 * HM], gRoSum[2 * HM];
__device__ float  gScale[2 * HM], gShift[2 * HM];

// ---------------- patch kernel smem layout (float indices) ----------------
constexpr int H1S  = 264;              // padded h1 row stride
constexpr int SH1  = 0;                // h1 [64 x 264] (rows 52..63 zeroed)
constexpr int ST   = 64 * H1S;         // t1 [52x64] then t2 [64x64]
constexpr int SFT  = ST + 64 * 64;     // feat [50x64] then u [52x64]
constexpr int SEW  = SFT + 3328;       // raw edge weights [200]
constexpr int SRTW = SEW + EPN;        // sorted weights [200]
constexpr int SRSO = SRTW + EPN;       // rsqrt deg_out [50]
constexpr int SRSI = SRSO + NPN;       // rsqrt deg_in  [50]
constexpr int SR0  = SRSI + NPN;       // r0[64] r1[256] r2[64] contiguous
constexpr int SR1  = SR0 + IN;
constexpr int SR2  = SR1 + HE;
constexpr int SGA  = SR2 + C2;         // scale [256]
constexpr int SGB  = SGA + HE;         // shift [256]
constexpr int SRED = SGB + HE;         // partials [256]
constexpr int SINT = SRED + HE;
constexpr int NI_SSRC = 0, NI_SDST = EPN, NI_SRTS = 2 * EPN;
constexpr int NI_START = 3 * EPN;      // [51]
constexpr int NI_FILL  = NI_START + NPN + 1;
constexpr int NI_CIN   = NI_FILL + NPN;
constexpr int NI_COUT  = NI_CIN + NPN;
constexpr int NINTS    = NI_COUT + NPN;
constexpr int SMEM_PATCH = (SINT + NINTS) * 4;   // ~107 KB -> 2 CTAs/SM

// =====================================================================
// Patch embedder: one CTA per patch, fused, f32x2-packed math.
// =====================================================================
__global__ void __launch_bounds__(256, 2) patch_kernel(
    const float* __restrict__ feats, const int* __restrict__ srcs,
    const int* __restrict__ dsts, const float* __restrict__ ews,
    const float* __restrict__ W1, const float* __restrict__ g1,
    const float* __restrict__ b1, const float* __restrict__ W2,
    const float* __restrict__ g2, const float* __restrict__ b2,
    const float* __restrict__ We)
{
    extern __shared__ float sm[];
    int* smi    = (int*)(sm + SINT);
    int* ssrc   = smi + NI_SSRC;
    int* sdst   = smi + NI_SDST;
    int* srts   = smi + NI_SRTS;
    int* sstart = smi + NI_START;
    int* sfill  = smi + NI_FILL;
    int* scin   = smi + NI_CIN;
    int* scout  = smi + NI_COUT;
    const int p = blockIdx.x, t = threadIdx.x;

    for (int i = t; i < EPN; i += 256) {
        ssrc[i] = srcs[p * EPN + i];
        sdst[i] = dsts[p * EPN + i];
        sm[SEW + i] = ews[p * EPN + i];
    }
    {
        const float4* f4 = (const float4*)(feats + (long long)p * NPN * IN);
        float4* s4 = (float4*)(sm + SFT);
        for (int i = t; i < NPN * IN / 4; i += 256) s4[i] = f4[i];
    }
    for (int i = t; i < NPN; i += 256) { scin[i] = 0; scout[i] = 0; sfill[i] = 0; }
    // zero h1 rows 52..63 (read by GEMM2's 64-row tiling)
    for (int i = t; i < 12 * H1S; i += 256) sm[SH1 + 52 * H1S + i] = 0.f;
    __syncthreads();

    if (t < EPN) { atomicAdd(&scout[ssrc[t]], 1); atomicAdd(&scin[sdst[t]], 1); }
    __syncthreads();
    if (t < NPN) {
        sm[SRSO + t] = rsqrtf((float)(scout[t] > 0 ? scout[t] : 1));
        sm[SRSI + t] = rsqrtf((float)(scin[t]  > 0 ? scin[t]  : 1));
    }
    if (t == 255) {  // serial 50-elem scan on a thread not used by r0
        int s = 0;
        for (int n = 0; n < NPN; n++) { sstart[n] = s; s += scin[n]; }
        sstart[NPN] = s;
    }
    if (t < IN) {  // r0 = feat.mean(0)
        float s = 0.f;
        for (int n = 0; n < NPN; n++) s += sm[SFT + n * IN + t];
        sm[SR0 + t] = s * (1.f / NPN);
    }
    __syncthreads();

    // counting sort by dst; fold rsqrt(deg_out[src]) into edge weight
    if (t < EPN) {
        int d = sdst[t];
        int pos = sstart[d] + atomicAdd(&sfill[d], 1);
        srts[pos] = ssrc[t];
        sm[SRTW + pos] = sm[SEW + t] * sm[SRSO + ssrc[t]];
    }
    __syncthreads();

    // gconv1 gather (channel-paired): t1[52 x 64], rows >= 50 zero
    for (int i = t; i < 52 * 32; i += 256) {
        int n = i >> 5, cp = (i & 31) << 1;
        u64 a = 0ull;
        if (n < NPN) {
            int e1 = sstart[n + 1];
            for (int e = sstart[n]; e < e1; ++e) {
                int s = srts[e];
                u64 ww; DUP2(ww, sm[SRTW + e]);
                u64 x = *(const u64*)(sm + SFT + s * IN + cp);
                FMA2(a, x, ww, a);
            }
            u64 rr; DUP2(rr, sm[SRSI + n]);
            MUL2(a, a, rr);
        }
        *(u64*)(sm + ST + n * IN + cp) = a;
    }
    __syncthreads();

    // GEMM1: h1[52 x 256(pad 264)] = t1[52x64] @ W1[64x256]  (f32x2)
    {
        int c0 = (t & 63) * 4, ng = t >> 6;
        u64 a0[13], a1[13];
        #pragma unroll
        for (int j = 0; j < 13; j++) { a0[j] = 0ull; a1[j] = 0ull; }
        for (int k = 0; k < IN; k++) {
            ulonglong2 w = __ldg((const ulonglong2*)(W1 + k * HE + c0));
            #pragma unroll
            for (int j = 0; j < 13; j++) {
                u64 xx; DUP2(xx, sm[ST + (ng + j * 4) * IN + k]);
                FMA2(a0[j], xx, w.x, a0[j]);
                FMA2(a1[j], xx, w.y, a1[j]);
            }
        }
        #pragma unroll
        for (int j = 0; j < 13; j++) {
            ulonglong2 o; o.x = a0[j]; o.y = a1[j];
            *(ulonglong2*)(sm + SH1 + (ng + j * 4) * H1S + c0) = o;
        }
    }
    __syncthreads();

    // graph_norm(g1,b1) + lrelu (rows < 50; rows 50..63 stay zero)
    if (t < HE) {
        float s = 0.f, s2 = 0.f;
        for (int n = 0; n < NPN; n++) { float v = sm[SH1 + n * H1S + t]; s += v; s2 = fmaf(v, v, s2); }
        float mu = s * (1.f / NPN), var = s2 * (1.f / NPN) - mu * mu;
        float sc = g1[t] * rsqrtf(var + EPSV);
        sm[SGA + t] = sc; sm[SGB + t] = b1[t] - mu * sc;
    }
    __syncthreads();
    for (int i = t; i < NPN * HE; i += 256) {
        int n = i >> 8, c = i & 255;
        float v = fmaf(sm[SH1 + n * H1S + c], sm[SGA + c], sm[SGB + c]);
        sm[SH1 + n * H1S + c] = v >= 0.f ? v : SLOPE * v;
    }
    __syncthreads();
    if (t < HE) {  // r1
        float s = 0.f;
        for (int n = 0; n < NPN; n++) s += sm[SH1 + n * H1S + t];
        sm[SR1 + t] = s * (1.f / NPN);
    }
    __syncthreads();

    // GEMM2: t2[64x64] = h1[64x264] @ W2[256x64]  (f32x2)
    {
        int c0 = (t & 15) * 4, rg = t >> 4;
        u64 a0[4], a1[4];
        #pragma unroll
        for (int j = 0; j < 4; j++) { a0[j] = 0ull; a1[j] = 0ull; }
        for (int k = 0; k < HE; k++) {
            ulonglong2 w = __ldg((const ulonglong2*)(W2 + k * C2 + c0));
            #pragma unroll
            for (int j = 0; j < 4; j++) {
                u64 xx; DUP2(xx, sm[SH1 + (rg + 16 * j) * H1S + k]);
                FMA2(a0[j], xx, w.x, a0[j]);
                FMA2(a1[j], xx, w.y, a1[j]);
            }
        }
        #pragma unroll
        for (int j = 0; j < 4; j++) {
            ulonglong2 o; o.x = a0[j]; o.y = a1[j];
            *(ulonglong2*)(sm + ST + (rg + 16 * j) * C2 + c0) = o;
        }
    }
    __syncthreads();

    // gconv2 gather (channel-paired) on 64 channels: u[52x64] at SFT
    for (int i = t; i < 52 * 32; i += 256) {
        int n = i >> 5, cp = (i & 31) << 1;
        u64 a = 0ull;
        if (n < NPN) {
            int e1 = sstart[n + 1];
            for (int e = sstart[n]; e < e1; ++e) {
                int s = srts[e];
                u64 ww; DUP2(ww, sm[SRTW + e]);
                u64 x = *(const u64*)(sm + ST + s * C2 + cp);
                FMA2(a, x, ww, a);
            }
            u64 rr; DUP2(rr, sm[SRSI + n]);
            MUL2(a, a, rr);
        }
        *(u64*)(sm + SFT + n * C2 + cp) = a;
    }
    __syncthreads();

    // graph_norm(g2,b2) + lrelu on u
    if (t < C2) {
        float s = 0.f, s2 = 0.f;
        for (int n = 0; n < NPN; n++) { float v = sm[SFT + n * C2 + t]; s += v; s2 = fmaf(v, v, s2); }
        float mu = s * (1.f / NPN), var = s2 * (1.f / NPN) - mu * mu;
        float sc = g2[t] * rsqrtf(var + EPSV);
        sm[SGA + t] = sc; sm[SGB + t] = b2[t] - mu * sc;
    }
    __syncthreads();
    for (int i = t; i < NPN * C2; i += 256) {
        int c = i & 63;
        float v = fmaf(sm[SFT + i], sm[SGA + c], sm[SGB + c]);
        sm[SFT + i] = v >= 0.f ? v : SLOPE * v;
    }
    __syncthreads();
    if (t < C2) {  // r2
        float s = 0.f;
        for (int n = 0; n < NPN; n++) s += sm[SFT + n * C2 + t];
        sm[SR2 + t] = s * (1.f / NPN);
    }
    __syncthreads();

    // emb = concat(r0,r1,r2)[384] @ We[384x128]
    {
        int j = t & 127, hf = t >> 7;
        float a = 0.f;
        int k0 = hf * 192;
        for (int k = k0; k < k0 + 192; k++)
            a = fmaf(sm[SR0 + k], __ldg(&We[k * RD + j]), a);
        sm[SRED + t] = a;
    }
    __syncthreads();
    float e = 0.f;
    if (t < RD) { e = sm[SRED + t] + sm[SRED + t + 128]; sm[SGB + t] = e; }
    __syncthreads();
    if (t < 32) {  // instance-norm stats over 128 channels (warp reduce)
        float s = 0.f, s2 = 0.f;
        #pragma unroll
        for (int i = 0; i < 4; i++) { float v = sm[SGB + t * 4 + i]; s += v; s2 = fmaf(v, v, s2); }
        #pragma unroll
        for (int o = 16; o; o >>= 1) {
            s  += __shfl_down_sync(0xffffffffu, s,  o);
            s2 += __shfl_down_sync(0xffffffffu, s2, o);
        }
        if (t == 0) {
            float mu = s * (1.f / RD), var = s2 * (1.f / RD) - mu * mu;
            sm[SGA] = mu; sm[SGA + 1] = rsqrtf(var + EPSV);
        }
    }
    __syncthreads();
    if (t < RD) {
        float y = (e - sm[SGA]) * sm[SGA + 1];
        y = y >= 0.f ? y : SLOPE * y;
        gEmb[p * RD + t] = y;
    }
}

// =====================================================================
// Mesh stage: CSR gather, f32x2 math
// =====================================================================
__global__ void init_zero() {
    int i = blockIdx.x * 256 + threadIdx.x;
    if (i < P) { gCntOut[i] = 0; gCntIn[i] = 0; gFill[i] = 0; }
    if (i < 2 * HM) { gSums[i] = 0.0; gSums2[i] = 0.0; gRoSum[i] = 0.0; }
}

__global__ void mesh_deg(const int* __restrict__ src, const int* __restrict__ dst) {
    int e = blockIdx.x * 256 + threadIdx.x;
    if (e < EM) { atomicAdd(&gCntOut[src[e]], 1); atomicAdd(&gCntIn[dst[e]], 1); }
}

__global__ void mesh_rs() {
    int i = blockIdx.x * 256 + threadIdx.x;
    if (i < P) {
        gRsOut[i] = rsqrtf((float)(gCntOut[i] > 0 ? gCntOut[i] : 1));
        gRsIn[i]  = rsqrtf((float)(gCntIn[i]  > 0 ? gCntIn[i]  : 1));
    }
}

__global__ void mesh_scan() {  // single block: exclusive scan of in-degrees
    __shared__ int part[256];
    int t = threadIdx.x;
    const int CH = (P + 255) / 256;
    int base = t * CH, s = 0;
    for (int i = 0; i < CH; i++) { int idx = base + i; if (idx < P) s += gCntIn[idx]; }
    part[t] = s; __syncthreads();
    for (int off = 1; off < 256; off <<= 1) {
        int v = (t >= off) ? part[t - off] : 0;
        __syncthreads();
        part[t] += v;
        __syncthreads();
    }
    int run = (t == 0) ? 0 : part[t - 1];
    for (int i = 0; i < CH; i++) {
        int idx = base + i;
        if (idx < P) { gOffs[idx] = run; run += gCntIn[idx]; }
    }
    if (t == 255) gOffs[P] = run;
}

__global__ void mesh_sort(const int* __restrict__ src, const int* __restrict__ dst,
                          const float* __restrict__ ew) {
    int e = blockIdx.x * 256 + threadIdx.x;
    if (e < EM) {
        int d = dst[e], s = src[e];
        int pos = gOffs[d] + atomicAdd(&gFill[d], 1);
        gSrtSrc[pos] = s;
        gSrtW[pos] = ew[e] * gRsOut[s];
    }
}

// gather, C=128: 4 nodes per block, 64 channel-pairs per node
__global__ void mesh_gather128(const float* __restrict__ X, float* __restrict__ Y) {
    int n = blockIdx.x * 4 + (threadIdx.x >> 6);
    int cp = (threadIdx.x & 63) * 2;
    int e1 = gOffs[n + 1];
    u64 a = 0ull;
    for (int e = gOffs[n]; e < e1; ++e) {
        u64 ww; DUP2(ww, gSrtW[e]);
        u64 x = __ldg((const u64*)(X + (long long)gSrtSrc[e] * 128 + cp));
        FMA2(a, x, ww, a);
    }
    u64 rr; DUP2(rr, gRsIn[n]);
    MUL2(a, a, rr);
    *(u64*)(Y + (long long)n * 128 + cp) = a;
}

// gather, C=256: 2 nodes per block, 128 channel-pairs per node
__global__ void mesh_gather256(const float* __restrict__ X, float* __restrict__ Y) {
    int n = blockIdx.x * 2 + (threadIdx.x >> 7);
    int cp = (threadIdx.x & 127) * 2;
    int e1 = gOffs[n + 1];
    u64 a = 0ull;
    for (int e = gOffs[n]; e < e1; ++e) {
        u64 ww; DUP2(ww, gSrtW[e]);
        u64 x = __ldg((const u64*)(X + (long long)gSrtSrc[e] * 256 + cp));
        FMA2(a, x, ww, a);
    }
    u64 rr; DUP2(rr, gRsIn[n]);
    MUL2(a, a, rr);
    *(u64*)(Y + (long long)n * 256 + cp) = a;
}

// Y[P x 256] = X[P x K] @ W[K x 256]  (f32x2)
template <int K>
__global__ void __launch_bounds__(256) mesh_gemm(const float* __restrict__ X,
                                                 const float* __restrict__ W,
                                                 float* __restrict__ Y) {
    __shared__ float xs[16 * K];
    int r0 = blockIdx.x * 16;
    int t = threadIdx.x;
    for (int i = t; i < 16 * K; i += 256)
        xs[i] = X[(long long)r0 * K + i];
    __syncthreads();
    int c0 = (t & 63) * 4, tr = t >> 6;
    u64 a0[4], a1[4];
    #pragma unroll
    for (int j = 0; j < 4; j++) { a0[j] = 0ull; a1[j] = 0ull; }
    for (int k = 0; k < K; k++) {
        ulonglong2 w = __ldg((const ulonglong2*)(W + k * HM + c0));
        #pragma unroll
        for (int j = 0; j < 4; j++) {
            u64 xx; DUP2(xx, xs[(tr + 4 * j) * K + k]);
            FMA2(a0[j], xx, w.x, a0[j]);
            FMA2(a1[j], xx, w.y, a1[j]);
        }
    }
    #pragma unroll
    for (int j = 0; j < 4; j++) {
        ulonglong2 o; o.x = a0[j]; o.y = a1[j];
        *(ulonglong2*)(Y + (long long)(r0 + tr + 4 * j) * HM + c0) = o;
    }
}

__global__ void mesh_stats(const float* __restrict__ Y, int off) {
    int c = threadIdx.x;
    int r0 = blockIdx.x * 50;
    float s = 0.f, s2 = 0.f;
    for (int i = 0; i < 50; i++) {
        float v = Y[(long long)(r0 + i) * HM + c];
        s += v; s2 = fmaf(v, v, s2);
    }
    atomicAdd(&gSums[off + c], (double)s);
    atomicAdd(&gSums2[off + c], (double)s2);
}

__global__ void mesh_finalize(const float* __restrict__ g, const float* __restrict__ b, int off) {
    int c = threadIdx.x;
    double mu = gSums[off + c] / P;
    double var = gSums2[off + c] / P - mu * mu;
    float sc = g[c] * rsqrtf((float)var + EPSV);
    gScale[off + c] = sc;
    gShift[off + c] = b[c] - (float)mu * sc;
}

__global__ void mesh_apply(float* __restrict__ Y, int off) {
    int c = threadIdx.x;
    int r0 = blockIdx.x * 50;
    float sc = gScale[off + c], sh = gShift[off + c];
    float s = 0.f;
    for (int i = 0; i < 50; i++) {
        long long idx = (long long)(r0 + i) * HM + c;
        float v = fmaf(Y[idx], sc, sh);
        v = v >= 0.f ? v : SLOPE * v;
        Y[idx] = v;
        s += v;
    }
    atomicAdd(&gRoSum[off + c], (double)s);
}

__global__ void final_kernel(const float* __restrict__ Wcls, float* __restrict__ out) {
    int t = threadIdx.x;
    if (t < OUTC) {
        float a = 0.f;
        for (int k = 0; k < 2 * HM; k++)
            a = fmaf((float)(gRoSum[k] / P), __ldg(&Wcls[k * OUTC + t]), a);
        out[t] = a;
    }
}

// =====================================================================
extern "C" void kernel_launch(void* const* d_in, const int* in_sizes, int n_in,
                              void* d_out, int out_size) {
    const float* patch_feats = (const float*)d_in[0];
    const int*   patch_src   = (const int*)d_in[1];
    const int*   patch_dst   = (const int*)d_in[2];
    const float* patch_ew    = (const float*)d_in[3];
    const int*   mesh_src    = (const int*)d_in[4];
    const int*   mesh_dst    = (const int*)d_in[5];
    const float* mesh_ew     = (const float*)d_in[6];
    const float* W1  = (const float*)d_in[7];
    const float* g1  = (const float*)d_in[8];
    const float* b1  = (const float*)d_in[9];
    const float* W2  = (const float*)d_in[10];
    const float* g2  = (const float*)d_in[11];
    const float* b2  = (const float*)d_in[12];
    const float* We  = (const float*)d_in[13];
    const float* Wc1 = (const float*)d_in[14];
    const float* g3  = (const float*)d_in[15];
    const float* b3  = (const float*)d_in[16];
    const float* Wc2 = (const float*)d_in[17];
    const float* g4  = (const float*)d_in[18];
    const float* b4  = (const float*)d_in[19];
    const float* Wcls = (const float*)d_in[20];
    float* out = (float*)d_out;

    cudaFuncSetAttribute(patch_kernel, cudaFuncAttributeMaxDynamicSharedMemorySize, SMEM_PATCH);

    void *pEmb, *pAgg1, *pAgg2, *pH, *pH2;
    cudaGetSymbolAddress(&pEmb,  gEmb);
    cudaGetSymbolAddress(&pAgg1, gAgg1);
    cudaGetSymbolAddress(&pAgg2, gAgg2);
    cudaGetSymbolAddress(&pH,    gH);
    cudaGetSymbolAddress(&pH2,   gH2);

    // patch_kernel placed 4th: ncu's -s 5 window (offset by 2 harness
    // launches, per last round's capture of my launch #4) lands on it.
    init_zero<<<(P + 255) / 256, 256>>>();
    mesh_deg<<<(EM + 255) / 256, 256>>>(mesh_src, mesh_dst);
    mesh_rs<<<(P + 255) / 256, 256>>>();

    patch_kernel<<<P, 256, SMEM_PATCH>>>(patch_feats, patch_src, patch_dst, patch_ew,
                                         W1, g1, b1, W2, g2, b2, We);

    mesh_scan<<<1, 256>>>();
    mesh_sort<<<(EM + 255) / 256, 256>>>(mesh_src, mesh_dst, mesh_ew);

    // mesh conv1
    mesh_gather128<<<P / 4, 256>>>((const float*)pEmb, (float*)pAgg1);
    mesh_gemm<RD><<<P / 16, 256>>>((const float*)pAgg1, Wc1, (float*)pH);
    mesh_stats<<<P / 50, 256>>>((const float*)pH, 0);
    mesh_finalize<<<1, 256>>>(g3, b3, 0);
    mesh_apply<<<P / 50, 256>>>((float*)pH, 0);

    // mesh conv2
    mesh_gather256<<<P / 2, 256>>>((const float*)pH, (float*)pAgg2);
    mesh_gemm<HM><<<P / 16, 256>>>((const float*)pAgg2, Wc2, (float*)pH2);
    mesh_stats<<<P / 50, 256>>>((const float*)pH2, HM);
    mesh_finalize<<<1, 256>>>(g4, b4, HM);
    mesh_apply<<<P / 50, 256>>>((float*)pH2, HM);

    final_kernel<<<1, 32>>>(Wcls, out);
}

// round 7
// speedup vs baseline: 2.4195x; 1.0896x over previous
#include <cuda_runtime.h>

// ---------------- problem constants ----------------
constexpr int P    = 10000;
constexpr int NPN  = 50;
constexpr int EPN  = 200;
constexpr int IN   = 64;
constexpr int HE   = 256;
constexpr int C2   = 64;
constexpr int RD   = 128;
constexpr int HM   = 256;
constexpr int OUTC = 16;
constexpr int EM   = 160000;
constexpr float EPSV  = 1e-5f;
constexpr float SLOPE = 0.01f;

// ---------------- packed fp32x2 helpers (sm_103a) ----------------
typedef unsigned long long u64;
#define FMA2(d, a, b, c) asm("fma.rn.f32x2 %0, %1, %2, %3;" : "=l"(d) : "l"(a), "l"(b), "l"(c))
#define MUL2(d, a, b)    asm("mul.rn.f32x2 %0, %1, %2;"     : "=l"(d) : "l"(a), "l"(b))
#define ADD2(d, a, b)    asm("add.rn.f32x2 %0, %1, %2;"     : "=l"(d) : "l"(a), "l"(b))
#define DUP2(d, x)       asm("mov.b64 %0, {%1, %1};"        : "=l"(d) : "r"(__float_as_uint(x)))

// ---------------- device scratch ----------------
__device__ float  gEmb[P * RD];
__device__ int    gCntOut[P], gCntIn[P], gFill[P];
__device__ int    gOffs[P + 1];
__device__ float  gRsOut[P], gRsIn[P];
__device__ int    gSrtSrc[EM];
__device__ float  gSrtW[EM];
__device__ float  gAgg1[P * RD];
__device__ float  gAgg2[P * HM];
__device__ float  gH[P * HM];
__device__ float  gH2[P * HM];
__device__ double gSums[2 * HM], gSums2[2 * HM], gRoSum[2 * HM];
__device__ float  gScale[2 * HM], gShift[2 * HM];

// ---------------- patch kernel smem layout (float indices) ----------------
constexpr int H1S  = 264;              // padded h1 row stride (16B-mult)
constexpr int SH1  = 0;                // h1 [64 x 264] (rows 52..63 zeroed)
constexpr int ST   = 64 * H1S;         // t1 [52x64] then t2 [64x64]
constexpr int SFT  = ST + 64 * 64;     // feat [50x64] then u [52x64]
constexpr int SEW  = SFT + 3328;       // raw edge weights [200]
constexpr int SRTW = SEW + EPN;        // sorted weights [200]
constexpr int SRSO = SRTW + EPN;       // rsqrt deg_out [50]
constexpr int SRSI = SRSO + NPN;       // rsqrt deg_in  [50]
constexpr int SR0  = SRSI + NPN;       // r0[64] r1[256] r2[64] contiguous
constexpr int SR1  = SR0 + IN;
constexpr int SR2  = SR1 + HE;
constexpr int SGA  = SR2 + C2;         // scale [256]  } also 512-float scratch
constexpr int SGB  = SGA + HE;         // shift [256]  } for readout partials
constexpr int SRED = SGB + HE;         // partials / emb [256]
constexpr int SINT = SRED + HE;
constexpr int NI_SSRC = 0, NI_SDST = EPN, NI_SRTS = 2 * EPN;
constexpr int NI_START = 3 * EPN;      // [51]
constexpr int NI_FILL  = NI_START + NPN + 1;
constexpr int NI_CIN   = NI_FILL + NPN;
constexpr int NI_COUT  = NI_CIN + NPN;
constexpr int NINTS    = NI_COUT + NPN;
constexpr int SMEM_PATCH = (SINT + NINTS) * 4;   // ~107 KB -> 2 CTAs/SM

// =====================================================================
// Patch embedder: one CTA per patch, fused, f32x2 math, vectorized LDS.
// =====================================================================
__global__ void __launch_bounds__(256, 2) patch_kernel(
    const float* __restrict__ feats, const int* __restrict__ srcs,
    const int* __restrict__ dsts, const float* __restrict__ ews,
    const float* __restrict__ W1, const float* __restrict__ g1,
    const float* __restrict__ b1, const float* __restrict__ W2,
    const float* __restrict__ g2, const float* __restrict__ b2,
    const float* __restrict__ We)
{
    extern __shared__ float sm[];
    int* smi    = (int*)(sm + SINT);
    int* ssrc   = smi + NI_SSRC;
    int* sdst   = smi + NI_SDST;
    int* srts   = smi + NI_SRTS;
    int* sstart = smi + NI_START;
    int* sfill  = smi + NI_FILL;
    int* scin   = smi + NI_CIN;
    int* scout  = smi + NI_COUT;
    const int p = blockIdx.x, t = threadIdx.x;

    for (int i = t; i < EPN; i += 256) {
        ssrc[i] = srcs[p * EPN + i];
        sdst[i] = dsts[p * EPN + i];
        sm[SEW + i] = ews[p * EPN + i];
    }
    {
        const float4* f4 = (const float4*)(feats + (long long)p * NPN * IN);
        float4* s4 = (float4*)(sm + SFT);
        for (int i = t; i < NPN * IN / 4; i += 256) s4[i] = f4[i];
    }
    for (int i = t; i < NPN; i += 256) { scin[i] = 0; scout[i] = 0; sfill[i] = 0; }
    // zero h1 rows 52..63 (read by GEMM2's 64-row tiling)
    for (int i = t; i < 12 * H1S; i += 256) sm[SH1 + 52 * H1S + i] = 0.f;
    __syncthreads();

    if (t < EPN) { atomicAdd(&scout[ssrc[t]], 1); atomicAdd(&scin[sdst[t]], 1); }
    __syncthreads();
    if (t < NPN) {
        sm[SRSO + t] = rsqrtf((float)(scout[t] > 0 ? scout[t] : 1));
        sm[SRSI + t] = rsqrtf((float)(scin[t]  > 0 ? scin[t]  : 1));
    }
    if (t == 255) {  // serial 50-elem scan on a thread not used by r0
        int s = 0;
        for (int n = 0; n < NPN; n++) { sstart[n] = s; s += scin[n]; }
        sstart[NPN] = s;
    }
    if (t < IN) {  // r0 = feat.mean(0)
        float s = 0.f;
        for (int n = 0; n < NPN; n++) s += sm[SFT + n * IN + t];
        sm[SR0 + t] = s * (1.f / NPN);
    }
    __syncthreads();

    // counting sort by dst; fold rsqrt(deg_out[src]) into edge weight
    if (t < EPN) {
        int d = sdst[t];
        int pos = sstart[d] + atomicAdd(&sfill[d], 1);
        srts[pos] = ssrc[t];
        sm[SRTW + pos] = sm[SEW + t] * sm[SRSO + ssrc[t]];
    }
    __syncthreads();

    // gconv1 gather (4 channels/thread): t1[52 x 64], rows >= 50 zero
    for (int i = t; i < 52 * 16; i += 256) {
        int n = i >> 4, cp = (i & 15) << 2;
        u64 a0 = 0ull, a1 = 0ull;
        if (n < NPN) {
            int e1 = sstart[n + 1];
            for (int e = sstart[n]; e < e1; ++e) {
                int s = srts[e];
                u64 ww; DUP2(ww, sm[SRTW + e]);
                ulonglong2 x = *(const ulonglong2*)(sm + SFT + s * IN + cp);
                FMA2(a0, x.x, ww, a0);
                FMA2(a1, x.y, ww, a1);
            }
            u64 rr; DUP2(rr, sm[SRSI + n]);
            MUL2(a0, a0, rr);
            MUL2(a1, a1, rr);
        }
        ulonglong2 o; o.x = a0; o.y = a1;
        *(ulonglong2*)(sm + ST + n * IN + cp) = o;
    }
    __syncthreads();

    // GEMM1: h1[52 x 256(pad 264)] = t1[52x64] @ W1[64x256]  (f32x2, k by 4)
    {
        int c0 = (t & 63) * 4, ng = t >> 6;
        u64 a0[13], a1[13];
        #pragma unroll
        for (int j = 0; j < 13; j++) { a0[j] = 0ull; a1[j] = 0ull; }
        for (int k4 = 0; k4 < IN / 4; k4++) {
            int k = k4 * 4;
            ulonglong2 w0 = __ldg((const ulonglong2*)(W1 + (k + 0) * HE + c0));
            ulonglong2 w1 = __ldg((const ulonglong2*)(W1 + (k + 1) * HE + c0));
            ulonglong2 w2 = __ldg((const ulonglong2*)(W1 + (k + 2) * HE + c0));
            ulonglong2 w3 = __ldg((const ulonglong2*)(W1 + (k + 3) * HE + c0));
            #pragma unroll
            for (int j = 0; j < 13; j++) {
                float4 x = *(const float4*)(sm + ST + (ng + j * 4) * IN + k);
                u64 d;
                DUP2(d, x.x); FMA2(a0[j], d, w0.x, a0[j]); FMA2(a1[j], d, w0.y, a1[j]);
                DUP2(d, x.y); FMA2(a0[j], d, w1.x, a0[j]); FMA2(a1[j], d, w1.y, a1[j]);
                DUP2(d, x.z); FMA2(a0[j], d, w2.x, a0[j]); FMA2(a1[j], d, w2.y, a1[j]);
                DUP2(d, x.w); FMA2(a0[j], d, w3.x, a0[j]); FMA2(a1[j], d, w3.y, a1[j]);
            }
        }
        #pragma unroll
        for (int j = 0; j < 13; j++) {
            ulonglong2 o; o.x = a0[j]; o.y = a1[j];
            *(ulonglong2*)(sm + SH1 + (ng + j * 4) * H1S + c0) = o;
        }
    }
    __syncthreads();

    // graph_norm(g1,b1) + lrelu (rows < 50; rows 50..63 stay zero)
    if (t < HE) {
        float s = 0.f, s2 = 0.f;
        for (int n = 0; n < NPN; n++) { float v = sm[SH1 + n * H1S + t]; s += v; s2 = fmaf(v, v, s2); }
        float mu = s * (1.f / NPN), var = s2 * (1.f / NPN) - mu * mu;
        float sc = g1[t] * rsqrtf(var + EPSV);
        sm[SGA + t] = sc; sm[SGB + t] = b1[t] - mu * sc;
    }
    __syncthreads();
    for (int i = t; i < NPN * HE; i += 256) {
        int n = i >> 8, c = i & 255;
        float v = fmaf(sm[SH1 + n * H1S + c], sm[SGA + c], sm[SGB + c]);
        sm[SH1 + n * H1S + c] = v >= 0.f ? v : SLOPE * v;
    }
    __syncthreads();
    if (t < HE) {  // r1
        float s = 0.f;
        for (int n = 0; n < NPN; n++) s += sm[SH1 + n * H1S + t];
        sm[SR1 + t] = s * (1.f / NPN);
    }
    __syncthreads();

    // GEMM2: t2[64x64] = h1[64x264] @ W2[256x64]  (f32x2, k by 4)
    {
        int c0 = (t & 15) * 4, rg = t >> 4;
        u64 a0[4], a1[4];
        #pragma unroll
        for (int j = 0; j < 4; j++) { a0[j] = 0ull; a1[j] = 0ull; }
        for (int k4 = 0; k4 < HE / 4; k4++) {
            int k = k4 * 4;
            ulonglong2 w0 = __ldg((const ulonglong2*)(W2 + (k + 0) * C2 + c0));
            ulonglong2 w1 = __ldg((const ulonglong2*)(W2 + (k + 1) * C2 + c0));
            ulonglong2 w2 = __ldg((const ulonglong2*)(W2 + (k + 2) * C2 + c0));
            ulonglong2 w3 = __ldg((const ulonglong2*)(W2 + (k + 3) * C2 + c0));
            #pragma unroll
            for (int j = 0; j < 4; j++) {
                float4 x = *(const float4*)(sm + SH1 + (rg + 16 * j) * H1S + k);
                u64 d;
                DUP2(d, x.x); FMA2(a0[j], d, w0.x, a0[j]); FMA2(a1[j], d, w0.y, a1[j]);
                DUP2(d, x.y); FMA2(a0[j], d, w1.x, a0[j]); FMA2(a1[j], d, w1.y, a1[j]);
                DUP2(d, x.z); FMA2(a0[j], d, w2.x, a0[j]); FMA2(a1[j], d, w2.y, a1[j]);
                DUP2(d, x.w); FMA2(a0[j], d, w3.x, a0[j]); FMA2(a1[j], d, w3.y, a1[j]);
            }
        }
        #pragma unroll
        for (int j = 0; j < 4; j++) {
            ulonglong2 o; o.x = a0[j]; o.y = a1[j];
            *(ulonglong2*)(sm + ST + (rg + 16 * j) * C2 + c0) = o;
        }
    }
    __syncthreads();

    // gconv2 gather (4 channels/thread) on 64 channels: u[52x64] at SFT
    for (int i = t; i < 52 * 16; i += 256) {
        int n = i >> 4, cp = (i & 15) << 2;
        u64 a0 = 0ull, a1 = 0ull;
        if (n < NPN) {
            int e1 = sstart[n + 1];
            for (int e = sstart[n]; e < e1; ++e) {
                int s = srts[e];
                u64 ww; DUP2(ww, sm[SRTW + e]);
                ulonglong2 x = *(const ulonglong2*)(sm + ST + s * C2 + cp);
                FMA2(a0, x.x, ww, a0);
                FMA2(a1, x.y, ww, a1);
            }
            u64 rr; DUP2(rr, sm[SRSI + n]);
            MUL2(a0, a0, rr);
            MUL2(a1, a1, rr);
        }
        ulonglong2 o; o.x = a0; o.y = a1;
        *(ulonglong2*)(sm + SFT + n * C2 + cp) = o;
    }
    __syncthreads();

    // graph_norm(g2,b2) + lrelu on u
    if (t < C2) {
        float s = 0.f, s2 = 0.f;
        for (int n = 0; n < NPN; n++) { float v = sm[SFT + n * C2 + t]; s += v; s2 = fmaf(v, v, s2); }
        float mu = s * (1.f / NPN), var = s2 * (1.f / NPN) - mu * mu;
        float sc = g2[t] * rsqrtf(var + EPSV);
        sm[SGA + t] = sc; sm[SGB + t] = b2[t] - mu * sc;
    }
    __syncthreads();
    for (int i = t; i < NPN * C2; i += 256) {
        int c = i & 63;
        float v = fmaf(sm[SFT + i], sm[SGA + c], sm[SGB + c]);
        sm[SFT + i] = v >= 0.f ? v : SLOPE * v;
    }
    __syncthreads();
    if (t < C2) {  // r2
        float s = 0.f;
        for (int n = 0; n < NPN; n++) s += sm[SFT + n * C2 + t];
        sm[SR2 + t] = s * (1.f / NPN);
    }
    __syncthreads();

    // emb = concat(r0,r1,r2)[384] @ We[384x128]  (f32x2 column pairs)
    // thread -> (jp = 2-col pair, hf = quarter of k); partials in SGA scratch
    {
        int jp = (t & 63) * 2, hf = t >> 6;
        int k0 = hf * 96;
        u64 a = 0ull;
        for (int k = k0; k < k0 + 96; k++) {
            u64 d; DUP2(d, sm[SR0 + k]);
            u64 w = __ldg((const u64*)(We + k * RD + jp));
            FMA2(a, d, w, a);
        }
        *(u64*)(sm + SGA + hf * 128 + jp) = a;   // SGA..SGB used as 512-f scratch
    }
    __syncthreads();
    if (t < 64) {  // reduce 4 partials -> emb pair, store to SRED
        u64 a  = *(const u64*)(sm + SGA + t * 2);
        u64 b_ = *(const u64*)(sm + SGA + 128 + t * 2);
        u64 c_ = *(const u64*)(sm + SGA + 256 + t * 2);
        u64 d_ = *(const u64*)(sm + SGA + 384 + t * 2);
        ADD2(a, a, b_); ADD2(c_, c_, d_); ADD2(a, a, c_);
        *(u64*)(sm + SRED + t * 2) = a;
    }
    __syncthreads();
    if (t < 32) {  // instance-norm stats over 128 channels (warp reduce)
        float s = 0.f, s2 = 0.f;
        #pragma unroll
        for (int i = 0; i < 4; i++) { float v = sm[SRED + t * 4 + i]; s += v; s2 = fmaf(v, v, s2); }
        #pragma unroll
        for (int o = 16; o; o >>= 1) {
            s  += __shfl_down_sync(0xffffffffu, s,  o);
            s2 += __shfl_down_sync(0xffffffffu, s2, o);
        }
        if (t == 0) {
            float mu = s * (1.f / RD), var = s2 * (1.f / RD) - mu * mu;
            sm[SGA] = mu; sm[SGA + 1] = rsqrtf(var + EPSV);
        }
    }
    __syncthreads();
    if (t < RD) {
        float y = (sm[SRED + t] - sm[SGA]) * sm[SGA + 1];
        y = y >= 0.f ? y : SLOPE * y;
        gEmb[p * RD + t] = y;
    }
}

// =====================================================================
// Mesh stage: CSR gather, f32x2 math, float4 loads
// =====================================================================
__global__ void init_zero() {
    int i = blockIdx.x * 256 + threadIdx.x;
    if (i < P) { gCntOut[i] = 0; gCntIn[i] = 0; gFill[i] = 0; }
    if (i < 2 * HM) { gSums[i] = 0.0; gSums2[i] = 0.0; gRoSum[i] = 0.0; }
}

__global__ void mesh_deg(const int* __restrict__ src, const int* __restrict__ dst) {
    int e = blockIdx.x * 256 + threadIdx.x;
    if (e < EM) { atomicAdd(&gCntOut[src[e]], 1); atomicAdd(&gCntIn[dst[e]], 1); }
}

__global__ void mesh_rs() {
    int i = blockIdx.x * 256 + threadIdx.x;
    if (i < P) {
        gRsOut[i] = rsqrtf((float)(gCntOut[i] > 0 ? gCntOut[i] : 1));
        gRsIn[i]  = rsqrtf((float)(gCntIn[i]  > 0 ? gCntIn[i]  : 1));
    }
}

__global__ void mesh_scan() {  // single block: exclusive scan of in-degrees
    __shared__ int part[256];
    int t = threadIdx.x;
    const int CH = (P + 255) / 256;
    int base = t * CH, s = 0;
    for (int i = 0; i < CH; i++) { int idx = base + i; if (idx < P) s += gCntIn[idx]; }
    part[t] = s; __syncthreads();
    for (int off = 1; off < 256; off <<= 1) {
        int v = (t >= off) ? part[t - off] : 0;
        __syncthreads();
        part[t] += v;
        __syncthreads();
    }
    int run = (t == 0) ? 0 : part[t - 1];
    for (int i = 0; i < CH; i++) {
        int idx = base + i;
        if (idx < P) { gOffs[idx] = run; run += gCntIn[idx]; }
    }
    if (t == 255) gOffs[P] = run;
}

__global__ void mesh_sort(const int* __restrict__ src, const int* __restrict__ dst,
                          const float* __restrict__ ew) {
    int e = blockIdx.x * 256 + threadIdx.x;
    if (e < EM) {
        int d = dst[e], s = src[e];
        int pos = gOffs[d] + atomicAdd(&gFill[d], 1);
        gSrtSrc[pos] = s;
        gSrtW[pos] = ew[e] * gRsOut[s];
    }
}

// gather, C=128: 8 nodes/block, 32 threads/node, 4 ch/thread
__global__ void mesh_gather128(const float* __restrict__ X, float* __restrict__ Y) {
    int n = blockIdx.x * 8 + (threadIdx.x >> 5);
    int cp = (threadIdx.x & 31) * 4;
    int e1 = gOffs[n + 1];
    u64 a0 = 0ull, a1 = 0ull;
    for (int e = gOffs[n]; e < e1; ++e) {
        u64 ww; DUP2(ww, gSrtW[e]);
        ulonglong2 x = __ldg((const ulonglong2*)(X + (long long)gSrtSrc[e] * 128 + cp));
        FMA2(a0, x.x, ww, a0);
        FMA2(a1, x.y, ww, a1);
    }
    u64 rr; DUP2(rr, gRsIn[n]);
    MUL2(a0, a0, rr); MUL2(a1, a1, rr);
    ulonglong2 o; o.x = a0; o.y = a1;
    *(ulonglong2*)(Y + (long long)n * 128 + cp) = o;
}

// gather, C=256: 4 nodes/block, 64 threads/node, 4 ch/thread
__global__ void mesh_gather256(const float* __restrict__ X, float* __restrict__ Y) {
    int n = blockIdx.x * 4 + (threadIdx.x >> 6);
    int cp = (threadIdx.x & 63) * 4;
    int e1 = gOffs[n + 1];
    u64 a0 = 0ull, a1 = 0ull;
    for (int e = gOffs[n]; e < e1; ++e) {
        u64 ww; DUP2(ww, gSrtW[e]);
        ulonglong2 x = __ldg((const ulonglong2*)(X + (long long)gSrtSrc[e] * 256 + cp));
        FMA2(a0, x.x, ww, a0);
        FMA2(a1, x.y, ww, a1);
    }
    u64 rr; DUP2(rr, gRsIn[n]);
    MUL2(a0, a0, rr); MUL2(a1, a1, rr);
    ulonglong2 o; o.x = a0; o.y = a1;
    *(ulonglong2*)(Y + (long long)n * 256 + cp) = o;
}

// Y[P x 256] = X[P x K] @ W[K x 256]  (f32x2, k by 4)
template <int K>
__global__ void __launch_bounds__(256) mesh_gemm(const float* __restrict__ X,
                                                 const float* __restrict__ W,
                                                 float* __restrict__ Y) {
    __shared__ float xs[16 * K];
    int r0 = blockIdx.x * 16;
    int t = threadIdx.x;
    for (int i = t; i < 16 * K; i += 256)
        xs[i] = X[(long long)r0 * K + i];
    __syncthreads();
    int c0 = (t & 63) * 4, tr = t >> 6;
    u64 a0[4], a1[4];
    #pragma unroll
    for (int j = 0; j < 4; j++) { a0[j] = 0ull; a1[j] = 0ull; }
    for (int k4 = 0; k4 < K / 4; k4++) {
        int k = k4 * 4;
        ulonglong2 w0 = __ldg((const ulonglong2*)(W + (k + 0) * HM + c0));
        ulonglong2 w1 = __ldg((const ulonglong2*)(W + (k + 1) * HM + c0));
        ulonglong2 w2 = __ldg((const ulonglong2*)(W + (k + 2) * HM + c0));
        ulonglong2 w3 = __ldg((const ulonglong2*)(W + (k + 3) * HM + c0));
        #pragma unroll
        for (int j = 0; j < 4; j++) {
            float4 x = *(const float4*)(xs + (tr + 4 * j) * K + k);
            u64 d;
            DUP2(d, x.x); FMA2(a0[j], d, w0.x, a0[j]); FMA2(a1[j], d, w0.y, a1[j]);
            DUP2(d, x.y); FMA2(a0[j], d, w1.x, a0[j]); FMA2(a1[j], d, w1.y, a1[j]);
            DUP2(d, x.z); FMA2(a0[j], d, w2.x, a0[j]); FMA2(a1[j], d, w2.y, a1[j]);
            DUP2(d, x.w); FMA2(a0[j], d, w3.x, a0[j]); FMA2(a1[j], d, w3.y, a1[j]);
        }
    }
    #pragma unroll
    for (int j = 0; j < 4; j++) {
        ulonglong2 o; o.x = a0[j]; o.y = a1[j];
        *(ulonglong2*)(Y + (long long)(r0 + tr + 4 * j) * HM + c0) = o;
    }
}

__global__ void mesh_stats(const float* __restrict__ Y, int off) {
    int c = threadIdx.x;
    int r0 = blockIdx.x * 50;
    float s = 0.f, s2 = 0.f;
    for (int i = 0; i < 50; i++) {
        float v = Y[(long long)(r0 + i) * HM + c];
        s += v; s2 = fmaf(v, v, s2);
    }
    atomicAdd(&gSums[off + c], (double)s);
    atomicAdd(&gSums2[off + c], (double)s2);
}

__global__ void mesh_finalize(const float* __restrict__ g, const float* __restrict__ b, int off) {
    int c = threadIdx.x;
    double mu = gSums[off + c] / P;
    double var = gSums2[off + c] / P - mu * mu;
    float sc = g[c] * rsqrtf((float)var + EPSV);
    gScale[off + c] = sc;
    gShift[off + c] = b[c] - (float)mu * sc;
}

__global__ void mesh_apply(float* __restrict__ Y, int off) {
    int c = threadIdx.x;
    int r0 = blockIdx.x * 50;
    float sc = gScale[off + c], sh = gShift[off + c];
    float s = 0.f;
    for (int i = 0; i < 50; i++) {
        long long idx = (long long)(r0 + i) * HM + c;
        float v = fmaf(Y[idx], sc, sh);
        v = v >= 0.f ? v : SLOPE * v;
        Y[idx] = v;
        s += v;
    }
    atomicAdd(&gRoSum[off + c], (double)s);
}

__global__ void final_kernel(const float* __restrict__ Wcls, float* __restrict__ out) {
    int t = threadIdx.x;
    if (t < OUTC) {
        float a = 0.f;
        for (int k = 0; k < 2 * HM; k++)
            a = fmaf((float)(gRoSum[k] / P), __ldg(&Wcls[k * OUTC + t]), a);
        out[t] = a;
    }
}

// =====================================================================
extern "C" void kernel_launch(void* const* d_in, const int* in_sizes, int n_in,
                              void* d_out, int out_size) {
    const float* patch_feats = (const float*)d_in[0];
    const int*   patch_src   = (const int*)d_in[1];
    const int*   patch_dst   = (const int*)d_in[2];
    const float* patch_ew    = (const float*)d_in[3];
    const int*   mesh_src    = (const int*)d_in[4];
    const int*   mesh_dst    = (const int*)d_in[5];
    const float* mesh_ew     = (const float*)d_in[6];
    const float* W1  = (const float*)d_in[7];
    const float* g1  = (const float*)d_in[8];
    const float* b1  = (const float*)d_in[9];
    const float* W2  = (const float*)d_in[10];
    const float* g2  = (const float*)d_in[11];
    const float* b2  = (const float*)d_in[12];
    const float* We  = (const float*)d_in[13];
    const float* Wc1 = (const float*)d_in[14];
    const float* g3  = (const float*)d_in[15];
    const float* b3  = (const float*)d_in[16];
    const float* Wc2 = (const float*)d_in[17];
    const float* g4  = (const float*)d_in[18];
    const float* b4  = (const float*)d_in[19];
    const float* Wcls = (const float*)d_in[20];
    float* out = (float*)d_out;

    cudaFuncSetAttribute(patch_kernel, cudaFuncAttributeMaxDynamicSharedMemorySize, SMEM_PATCH);

    void *pEmb, *pAgg1, *pAgg2, *pH, *pH2;
    cudaGetSymbolAddress(&pEmb,  gEmb);
    cudaGetSymbolAddress(&pAgg1, gAgg1);
    cudaGetSymbolAddress(&pAgg2, gAgg2);
    cudaGetSymbolAddress(&pH,    gH);
    cudaGetSymbolAddress(&pH2,   gH2);

    // keep patch_kernel as 4th launch so ncu's window lands on it
    init_zero<<<(P + 255) / 256, 256>>>();
    mesh_deg<<<(EM + 255) / 256, 256>>>(mesh_src, mesh_dst);
    mesh_rs<<<(P + 255) / 256, 256>>>();

    patch_kernel<<<P, 256, SMEM_PATCH>>>(patch_feats, patch_src, patch_dst, patch_ew,
                                         W1, g1, b1, W2, g2, b2, We);

    mesh_scan<<<1, 256>>>();
    mesh_sort<<<(EM + 255) / 256, 256>>>(mesh_src, mesh_dst, mesh_ew);

    // mesh conv1
    mesh_gather128<<<P / 8, 256>>>((const float*)pEmb, (float*)pAgg1);
    mesh_gemm<RD><<<P / 16, 256>>>((const float*)pAgg1, Wc1, (float*)pH);
    mesh_stats<<<P / 50, 256>>>((const float*)pH, 0);
    mesh_finalize<<<1, 256>>>(g3, b3, 0);
    mesh_apply<<<P / 50, 256>>>((float*)pH, 0);

    // mesh conv2
    mesh_gather256<<<P / 4, 256>>>((const float*)pH, (float*)pAgg2);
    mesh_gemm<HM><<<P / 16, 256>>>((const float*)pAgg2, Wc2, (float*)pH2);
    mesh_stats<<<P / 50, 256>>>((const float*)pH2, HM);
    mesh_finalize<<<1, 256>>>(g4, b4, HM);
    mesh_apply<<<P / 50, 256>>>((float*)pH2, HM);

    final_kernel<<<1, 32>>>(Wcls, out);
}

// round 8
// speedup vs baseline: 2.4582x; 1.0160x over previous
#include <cuda_runtime.h>

// ---------------- problem constants ----------------
constexpr int P    = 10000;
constexpr int NPN  = 50;
constexpr int EPN  = 200;
constexpr int IN   = 64;
constexpr int HE   = 256;
constexpr int C2   = 64;
constexpr int RD   = 128;
constexpr int HM   = 256;
constexpr int OUTC = 16;
constexpr int EM   = 160000;
constexpr float EPSV  = 1e-5f;
constexpr float SLOPE = 0.01f;
constexpr int TPB  = 512;   // patch kernel threads

// ---------------- packed fp32x2 helpers (sm_103a) ----------------
typedef unsigned long long u64;
#define FMA2(d, a, b, c) asm("fma.rn.f32x2 %0, %1, %2, %3;" : "=l"(d) : "l"(a), "l"(b), "l"(c))
#define MUL2(d, a, b)    asm("mul.rn.f32x2 %0, %1, %2;"     : "=l"(d) : "l"(a), "l"(b))
#define ADD2(d, a, b)    asm("add.rn.f32x2 %0, %1, %2;"     : "=l"(d) : "l"(a), "l"(b))
#define DUP2(d, x)       asm("mov.b64 %0, {%1, %1};"        : "=l"(d) : "r"(__float_as_uint(x)))

// ---------------- device scratch ----------------
__device__ float  gEmb[P * RD];
__device__ int    gCntOut[P], gCntIn[P], gFill[P];
__device__ int    gOffs[P + 1];
__device__ float  gRsOut[P], gRsIn[P];
__device__ int    gSrtSrc[EM];
__device__ float  gSrtW[EM];
__device__ float  gAgg1[P * RD];
__device__ float  gAgg2[P * HM];
__device__ float  gH[P * HM];
__device__ float  gH2[P * HM];
__device__ double gSums[2 * HM], gSums2[2 * HM], gRoSum[2 * HM];
__device__ float  gScale[2 * HM], gShift[2 * HM];

// ---------------- patch kernel smem layout (float indices) ----------------
constexpr int H1S  = 264;              // padded h1 row stride (16B-mult)
constexpr int SH1  = 0;                // h1 [64 x 264] (rows 52..63 zero)
constexpr int ST   = 64 * H1S;         // t1 [56x64] then t2 [64x64]; also readout partials
constexpr int SFT  = ST + 64 * 64;     // feat [50x64] then u [52x64]
constexpr int SEW  = SFT + 3328;       // raw edge weights [200]
constexpr int SRTW = SEW + EPN;        // sorted weights [200]
constexpr int SRSO = SRTW + EPN;       // rsqrt deg_out [50]
constexpr int SRSI = SRSO + NPN;       // rsqrt deg_in  [50]
constexpr int SR0  = SRSI + NPN;       // r0[64] r1[256] r2[64] contiguous
constexpr int SR1  = SR0 + IN;
constexpr int SR2  = SR1 + HE;
constexpr int SGA  = SR2 + C2;         // scale [256]
constexpr int SGB  = SGA + HE;         // shift [256]
constexpr int SRED = SGB + HE;         // emb [256]
constexpr int SINT = SRED + HE;
constexpr int NI_SSRC = 0, NI_SDST = EPN, NI_SRTS = 2 * EPN;
constexpr int NI_START = 3 * EPN;      // [51]
constexpr int NI_FILL  = NI_START + NPN + 1;
constexpr int NI_CIN   = NI_FILL + NPN;
constexpr int NI_COUT  = NI_CIN + NPN;
constexpr int NINTS    = NI_COUT + NPN;
constexpr int SMEM_PATCH = (SINT + NINTS) * 4;   // ~107 KB -> 2 CTAs/SM

// =====================================================================
// Patch embedder: one CTA per patch, 512 threads, f32x2 math.
// =====================================================================
__global__ void __launch_bounds__(TPB, 2) patch_kernel(
    const float* __restrict__ feats, const int* __restrict__ srcs,
    const int* __restrict__ dsts, const float* __restrict__ ews,
    const float* __restrict__ W1, const float* __restrict__ g1,
    const float* __restrict__ b1, const float* __restrict__ W2,
    const float* __restrict__ g2, const float* __restrict__ b2,
    const float* __restrict__ We)
{
    extern __shared__ float sm[];
    int* smi    = (int*)(sm + SINT);
    int* ssrc   = smi + NI_SSRC;
    int* sdst   = smi + NI_SDST;
    int* srts   = smi + NI_SRTS;
    int* sstart = smi + NI_START;
    int* sfill  = smi + NI_FILL;
    int* scin   = smi + NI_CIN;
    int* scout  = smi + NI_COUT;
    const int p = blockIdx.x, t = threadIdx.x;

    for (int i = t; i < EPN; i += TPB) {
        ssrc[i] = srcs[p * EPN + i];
        sdst[i] = dsts[p * EPN + i];
        sm[SEW + i] = ews[p * EPN + i];
    }
    {
        const float4* f4 = (const float4*)(feats + (long long)p * NPN * IN);
        float4* s4 = (float4*)(sm + SFT);
        for (int i = t; i < NPN * IN / 4; i += TPB) s4[i] = f4[i];
    }
    for (int i = t; i < NPN; i += TPB) { scin[i] = 0; scout[i] = 0; sfill[i] = 0; }
    // zero h1 rows 52..63 (GEMM2 reads a full 64-row tile)
    for (int i = t; i < 12 * H1S; i += TPB) sm[SH1 + 52 * H1S + i] = 0.f;
    __syncthreads();

    if (t < EPN) { atomicAdd(&scout[ssrc[t]], 1); atomicAdd(&scin[sdst[t]], 1); }
    __syncthreads();
    if (t < NPN) {
        sm[SRSO + t] = rsqrtf((float)(scout[t] > 0 ? scout[t] : 1));
        sm[SRSI + t] = rsqrtf((float)(scin[t]  > 0 ? scin[t]  : 1));
    }
    if (t == TPB - 1) {  // serial 50-elem scan
        int s = 0;
        for (int n = 0; n < NPN; n++) { sstart[n] = s; s += scin[n]; }
        sstart[NPN] = s;
    }
    if (t < IN) {  // r0 = feat.mean(0)
        float s = 0.f;
        for (int n = 0; n < NPN; n++) s += sm[SFT + n * IN + t];
        sm[SR0 + t] = s * (1.f / NPN);
    }
    __syncthreads();

    // counting sort by dst; fold rsqrt(deg_out[src]) into edge weight
    if (t < EPN) {
        int d = sdst[t];
        int pos = sstart[d] + atomicAdd(&sfill[d], 1);
        srts[pos] = ssrc[t];
        sm[SRTW + pos] = sm[SEW + t] * sm[SRSO + ssrc[t]];
    }
    __syncthreads();

    // gconv1 gather (4 ch/thread): t1[56 x 64], rows >= 50 zero
    for (int i = t; i < 56 * 16; i += TPB) {
        int n = i >> 4, cp = (i & 15) << 2;
        u64 a0 = 0ull, a1 = 0ull;
        if (n < NPN) {
            int e1 = sstart[n + 1];
            for (int e = sstart[n]; e < e1; ++e) {
                int s = srts[e];
                u64 ww; DUP2(ww, sm[SRTW + e]);
                ulonglong2 x = *(const ulonglong2*)(sm + SFT + s * IN + cp);
                FMA2(a0, x.x, ww, a0);
                FMA2(a1, x.y, ww, a1);
            }
            u64 rr; DUP2(rr, sm[SRSI + n]);
            MUL2(a0, a0, rr);
            MUL2(a1, a1, rr);
        }
        ulonglong2 o; o.x = a0; o.y = a1;
        *(ulonglong2*)(sm + ST + n * IN + cp) = o;
    }
    __syncthreads();

    // GEMM1: h1[56 x 256(pad 264)] = t1[56x64] @ W1[64x256]
    // 64 col-groups (4 cols) x 8 row-groups (7 rows: rg + 8j)
    {
        int c0 = (t & 63) * 4, rg = t >> 6;
        u64 a0[7], a1[7];
        #pragma unroll
        for (int j = 0; j < 7; j++) { a0[j] = 0ull; a1[j] = 0ull; }
        for (int k4 = 0; k4 < IN / 4; k4++) {
            int k = k4 * 4;
            ulonglong2 w0 = __ldg((const ulonglong2*)(W1 + (k + 0) * HE + c0));
            ulonglong2 w1 = __ldg((const ulonglong2*)(W1 + (k + 1) * HE + c0));
            ulonglong2 w2 = __ldg((const ulonglong2*)(W1 + (k + 2) * HE + c0));
            ulonglong2 w3 = __ldg((const ulonglong2*)(W1 + (k + 3) * HE + c0));
            #pragma unroll
            for (int j = 0; j < 7; j++) {
                float4 x = *(const float4*)(sm + ST + (rg + j * 8) * IN + k);
                u64 d;
                DUP2(d, x.x); FMA2(a0[j], d, w0.x, a0[j]); FMA2(a1[j], d, w0.y, a1[j]);
                DUP2(d, x.y); FMA2(a0[j], d, w1.x, a0[j]); FMA2(a1[j], d, w1.y, a1[j]);
                DUP2(d, x.z); FMA2(a0[j], d, w2.x, a0[j]); FMA2(a1[j], d, w2.y, a1[j]);
                DUP2(d, x.w); FMA2(a0[j], d, w3.x, a0[j]); FMA2(a1[j], d, w3.y, a1[j]);
            }
        }
        #pragma unroll
        for (int j = 0; j < 7; j++) {
            ulonglong2 o; o.x = a0[j]; o.y = a1[j];
            *(ulonglong2*)(sm + SH1 + (rg + j * 8) * H1S + c0) = o;
        }
    }
    __syncthreads();

    // graph_norm(g1,b1) + lrelu (rows < 50 only; pads stay zero)
    if (t < HE) {
        float s = 0.f, s2 = 0.f;
        for (int n = 0; n < NPN; n++) { float v = sm[SH1 + n * H1S + t]; s += v; s2 = fmaf(v, v, s2); }
        float mu = s * (1.f / NPN), var = s2 * (1.f / NPN) - mu * mu;
        float sc = g1[t] * rsqrtf(var + EPSV);
        sm[SGA + t] = sc; sm[SGB + t] = b1[t] - mu * sc;
    }
    __syncthreads();
    for (int i = t; i < NPN * HE; i += TPB) {
        int n = i >> 8, c = i & 255;
        float v = fmaf(sm[SH1 + n * H1S + c], sm[SGA + c], sm[SGB + c]);
        sm[SH1 + n * H1S + c] = v >= 0.f ? v : SLOPE * v;
    }
    __syncthreads();
    if (t < HE) {  // r1
        float s = 0.f;
        for (int n = 0; n < NPN; n++) s += sm[SH1 + n * H1S + t];
        sm[SR1 + t] = s * (1.f / NPN);
    }
    __syncthreads();

    // GEMM2: t2[64x64] = h1[64x264] @ W2[256x64]
    // 16 colg (4 cols) x 16 rowg (4 rows: rg + 16j) x 2-way K-split,
    // reduced in-warp via shfl_xor(16).
    {
        int c0 = (t & 15) * 4;
        int ks = (t >> 4) & 1;
        int rg = t >> 5;               // 0..15
        u64 a0[4], a1[4];
        #pragma unroll
        for (int j = 0; j < 4; j++) { a0[j] = 0ull; a1[j] = 0ull; }
        int k4b = ks * 32;
        for (int k4 = k4b; k4 < k4b + 32; k4++) {
            int k = k4 * 4;
            ulonglong2 w0 = __ldg((const ulonglong2*)(W2 + (k + 0) * C2 + c0));
            ulonglong2 w1 = __ldg((const ulonglong2*)(W2 + (k + 1) * C2 + c0));
            ulonglong2 w2 = __ldg((const ulonglong2*)(W2 + (k + 2) * C2 + c0));
            ulonglong2 w3 = __ldg((const ulonglong2*)(W2 + (k + 3) * C2 + c0));
            #pragma unroll
            for (int j = 0; j < 4; j++) {
                float4 x = *(const float4*)(sm + SH1 + (rg + 16 * j) * H1S + k);
                u64 d;
                DUP2(d, x.x); FMA2(a0[j], d, w0.x, a0[j]); FMA2(a1[j], d, w0.y, a1[j]);
                DUP2(d, x.y); FMA2(a0[j], d, w1.x, a0[j]); FMA2(a1[j], d, w1.y, a1[j]);
                DUP2(d, x.z); FMA2(a0[j], d, w2.x, a0[j]); FMA2(a1[j], d, w2.y, a1[j]);
                DUP2(d, x.w); FMA2(a0[j], d, w3.x, a0[j]); FMA2(a1[j], d, w3.y, a1[j]);
            }
        }
        #pragma unroll
        for (int j = 0; j < 4; j++) {
            float2 v0 = *(float2*)&a0[j];
            float2 v1 = *(float2*)&a1[j];
            v0.x += __shfl_xor_sync(0xffffffffu, v0.x, 16);
            v0.y += __shfl_xor_sync(0xffffffffu, v0.y, 16);
            v1.x += __shfl_xor_sync(0xffffffffu, v1.x, 16);
            v1.y += __shfl_xor_sync(0xffffffffu, v1.y, 16);
            if (ks == 0) {
                float4 o = make_float4(v0.x, v0.y, v1.x, v1.y);
                *(float4*)(sm + ST + (rg + 16 * j) * C2 + c0) = o;
            }
        }
    }
    __syncthreads();

    // gconv2 gather (4 ch/thread) on 64 channels: u[52x64] at SFT
    for (int i = t; i < 52 * 16; i += TPB) {
        int n = i >> 4, cp = (i & 15) << 2;
        u64 a0 = 0ull, a1 = 0ull;
        if (n < NPN) {
            int e1 = sstart[n + 1];
            for (int e = sstart[n]; e < e1; ++e) {
                int s = srts[e];
                u64 ww; DUP2(ww, sm[SRTW + e]);
                ulonglong2 x = *(const ulonglong2*)(sm + ST + s * C2 + cp);
                FMA2(a0, x.x, ww, a0);
                FMA2(a1, x.y, ww, a1);
            }
            u64 rr; DUP2(rr, sm[SRSI + n]);
            MUL2(a0, a0, rr);
            MUL2(a1, a1, rr);
        }
        ulonglong2 o; o.x = a0; o.y = a1;
        *(ulonglong2*)(sm + SFT + n * C2 + cp) = o;
    }
    __syncthreads();

    // graph_norm(g2,b2) + lrelu on u
    if (t < C2) {
        float s = 0.f, s2 = 0.f;
        for (int n = 0; n < NPN; n++) { float v = sm[SFT + n * C2 + t]; s += v; s2 = fmaf(v, v, s2); }
        float mu = s * (1.f / NPN), var = s2 * (1.f / NPN) - mu * mu;
        float sc = g2[t] * rsqrtf(var + EPSV);
        sm[SGA + t] = sc; sm[SGB + t] = b2[t] - mu * sc;
    }
    __syncthreads();
    for (int i = t; i < NPN * C2; i += TPB) {
        int c = i & 63;
        float v = fmaf(sm[SFT + i], sm[SGA + c], sm[SGB + c]);
        sm[SFT + i] = v >= 0.f ? v : SLOPE * v;
    }
    __syncthreads();
    if (t < C2) {  // r2
        float s = 0.f;
        for (int n = 0; n < NPN; n++) s += sm[SFT + n * C2 + t];
        sm[SR2 + t] = s * (1.f / NPN);
    }
    __syncthreads();

    // emb = concat(r0,r1,r2)[384] @ We[384x128]  (8 k-groups of 48)
    // partials in ST (t2 is dead after gconv2)
    {
        int jp = (t & 63) * 2, hf = t >> 6;
        int k0 = hf * 48;
        u64 a = 0ull;
        for (int k = k0; k < k0 + 48; k++) {
            u64 d; DUP2(d, sm[SR0 + k]);
            u64 w = __ldg((const u64*)(We + k * RD + jp));
            FMA2(a, d, w, a);
        }
        *(u64*)(sm + ST + hf * 128 + jp) = a;
    }
    __syncthreads();
    if (t < 64) {  // reduce 8 partials -> emb pair at SRED
        u64 a = *(const u64*)(sm + ST + t * 2);
        #pragma unroll
        for (int h = 1; h < 8; h++) {
            u64 b_ = *(const u64*)(sm + ST + h * 128 + t * 2);
            ADD2(a, a, b_);
        }
        *(u64*)(sm + SRED + t * 2) = a;
    }
    __syncthreads();
    if (t < 32) {  // instance-norm stats over 128 channels (warp reduce)
        float s = 0.f, s2 = 0.f;
        #pragma unroll
        for (int i = 0; i < 4; i++) { float v = sm[SRED + t * 4 + i]; s += v; s2 = fmaf(v, v, s2); }
        #pragma unroll
        for (int o = 16; o; o >>= 1) {
            s  += __shfl_down_sync(0xffffffffu, s,  o);
            s2 += __shfl_down_sync(0xffffffffu, s2, o);
        }
        if (t == 0) {
            float mu = s * (1.f / RD), var = s2 * (1.f / RD) - mu * mu;
            sm[SGA] = mu; sm[SGA + 1] = rsqrtf(var + EPSV);
        }
    }
    __syncthreads();
    if (t < RD) {
        float y = (sm[SRED + t] - sm[SGA]) * sm[SGA + 1];
        y = y >= 0.f ? y : SLOPE * y;
        gEmb[p * RD + t] = y;
    }
}

// =====================================================================
// Mesh stage: CSR gather, f32x2 math, float4 loads
// =====================================================================
__global__ void init_zero() {
    int i = blockIdx.x * 256 + threadIdx.x;
    if (i < P) { gCntOut[i] = 0; gCntIn[i] = 0; gFill[i] = 0; }
    if (i < 2 * HM) { gSums[i] = 0.0; gSums2[i] = 0.0; gRoSum[i] = 0.0; }
}

__global__ void mesh_deg(const int* __restrict__ src, const int* __restrict__ dst) {
    int e = blockIdx.x * 256 + threadIdx.x;
    if (e < EM) { atomicAdd(&gCntOut[src[e]], 1); atomicAdd(&gCntIn[dst[e]], 1); }
}

__global__ void mesh_rs() {
    int i = blockIdx.x * 256 + threadIdx.x;
    if (i < P) {
        gRsOut[i] = rsqrtf((float)(gCntOut[i] > 0 ? gCntOut[i] : 1));
        gRsIn[i]  = rsqrtf((float)(gCntIn[i]  > 0 ? gCntIn[i]  : 1));
    }
}

__global__ void mesh_scan() {  // single block: exclusive scan of in-degrees
    __shared__ int part[256];
    int t = threadIdx.x;
    const int CH = (P + 255) / 256;
    int base = t * CH, s = 0;
    for (int i = 0; i < CH; i++) { int idx = base + i; if (idx < P) s += gCntIn[idx]; }
    part[t] = s; __syncthreads();
    for (int off = 1; off < 256; off <<= 1) {
        int v = (t >= off) ? part[t - off] : 0;
        __syncthreads();
        part[t] += v;
        __syncthreads();
    }
    int run = (t == 0) ? 0 : part[t - 1];
    for (int i = 0; i < CH; i++) {
        int idx = base + i;
        if (idx < P) { gOffs[idx] = run; run += gCntIn[idx]; }
    }
    if (t == 255) gOffs[P] = run;
}

__global__ void mesh_sort(const int* __restrict__ src, const int* __restrict__ dst,
                          const float* __restrict__ ew) {
    int e = blockIdx.x * 256 + threadIdx.x;
    if (e < EM) {
        int d = dst[e], s = src[e];
        int pos = gOffs[d] + atomicAdd(&gFill[d], 1);
        gSrtSrc[pos] = s;
        gSrtW[pos] = ew[e] * gRsOut[s];
    }
}

__global__ void mesh_gather128(const float* __restrict__ X, float* __restrict__ Y) {
    int n = blockIdx.x * 8 + (threadIdx.x >> 5);
    int cp = (threadIdx.x & 31) * 4;
    int e1 = gOffs[n + 1];
    u64 a0 = 0ull, a1 = 0ull;
    for (int e = gOffs[n]; e < e1; ++e) {
        u64 ww; DUP2(ww, gSrtW[e]);
        ulonglong2 x = __ldg((const ulonglong2*)(X + (long long)gSrtSrc[e] * 128 + cp));
        FMA2(a0, x.x, ww, a0);
        FMA2(a1, x.y, ww, a1);
    }
    u64 rr; DUP2(rr, gRsIn[n]);
    MUL2(a0, a0, rr); MUL2(a1, a1, rr);
    ulonglong2 o; o.x = a0; o.y = a1;
    *(ulonglong2*)(Y + (long long)n * 128 + cp) = o;
}

__global__ void mesh_gather256(const float* __restrict__ X, float* __restrict__ Y) {
    int n = blockIdx.x * 4 + (threadIdx.x >> 6);
    int cp = (threadIdx.x & 63) * 4;
    int e1 = gOffs[n + 1];
    u64 a0 = 0ull, a1 = 0ull;
    for (int e = gOffs[n]; e < e1; ++e) {
        u64 ww; DUP2(ww, gSrtW[e]);
        ulonglong2 x = __ldg((const ulonglong2*)(X + (long long)gSrtSrc[e] * 256 + cp));
        FMA2(a0, x.x, ww, a0);
        FMA2(a1, x.y, ww, a1);
    }
    u64 rr; DUP2(rr, gRsIn[n]);
    MUL2(a0, a0, rr); MUL2(a1, a1, rr);
    ulonglong2 o; o.x = a0; o.y = a1;
    *(ulonglong2*)(Y + (long long)n * 256 + cp) = o;
}

template <int K>
__global__ void __launch_bounds__(256) mesh_gemm(const float* __restrict__ X,
                                                 const float* __restrict__ W,
                                                 float* __restrict__ Y) {
    __shared__ float xs[16 * K];
    int r0 = blockIdx.x * 16;
    int t = threadIdx.x;
    for (int i = t; i < 16 * K; i += 256)
        xs[i] = X[(long long)r0 * K + i];
    __syncthreads();
    int c0 = (t & 63) * 4, tr = t >> 6;
    u64 a0[4], a1[4];
    #pragma unroll
    for (int j = 0; j < 4; j++) { a0[j] = 0ull; a1[j] = 0ull; }
    for (int k4 = 0; k4 < K / 4; k4++) {
        int k = k4 * 4;
        ulonglong2 w0 = __ldg((const ulonglong2*)(W + (k + 0) * HM + c0));
        ulonglong2 w1 = __ldg((const ulonglong2*)(W + (k + 1) * HM + c0));
        ulonglong2 w2 = __ldg((const ulonglong2*)(W + (k + 2) * HM + c0));
        ulonglong2 w3 = __ldg((const ulonglong2*)(W + (k + 3) * HM + c0));
        #pragma unroll
        for (int j = 0; j < 4; j++) {
            float4 x = *(const float4*)(xs + (tr + 4 * j) * K + k);
            u64 d;
            DUP2(d, x.x); FMA2(a0[j], d, w0.x, a0[j]); FMA2(a1[j], d, w0.y, a1[j]);
            DUP2(d, x.y); FMA2(a0[j], d, w1.x, a0[j]); FMA2(a1[j], d, w1.y, a1[j]);
            DUP2(d, x.z); FMA2(a0[j], d, w2.x, a0[j]); FMA2(a1[j], d, w2.y, a1[j]);
            DUP2(d, x.w); FMA2(a0[j], d, w3.x, a0[j]); FMA2(a1[j], d, w3.y, a1[j]);
        }
    }
    #pragma unroll
    for (int j = 0; j < 4; j++) {
        ulonglong2 o; o.x = a0[j]; o.y = a1[j];
        *(ulonglong2*)(Y + (long long)(r0 + tr + 4 * j) * HM + c0) = o;
    }
}

__global__ void mesh_stats(const float* __restrict__ Y, int off) {
    int c = threadIdx.x;
    int r0 = blockIdx.x * 50;
    float s = 0.f, s2 = 0.f;
    for (int i = 0; i < 50; i++) {
        float v = Y[(long long)(r0 + i) * HM + c];
        s += v; s2 = fmaf(v, v, s2);
    }
    atomicAdd(&gSums[off + c], (double)s);
    atomicAdd(&gSums2[off + c], (double)s2);
}

__global__ void mesh_finalize(const float* __restrict__ g, const float* __restrict__ b, int off) {
    int c = threadIdx.x;
    double mu = gSums[off + c] / P;
    double var = gSums2[off + c] / P - mu * mu;
    float sc = g[c] * rsqrtf((float)var + EPSV);
    gScale[off + c] = sc;
    gShift[off + c] = b[c] - (float)mu * sc;
}

__global__ void mesh_apply(float* __restrict__ Y, int off) {
    int c = threadIdx.x;
    int r0 = blockIdx.x * 50;
    float sc = gScale[off + c], sh = gShift[off + c];
    float s = 0.f;
    for (int i = 0; i < 50; i++) {
        long long idx = (long long)(r0 + i) * HM + c;
        float v = fmaf(Y[idx], sc, sh);
        v = v >= 0.f ? v : SLOPE * v;
        Y[idx] = v;
        s += v;
    }
    atomicAdd(&gRoSum[off + c], (double)s);
}

__global__ void final_kernel(const float* __restrict__ Wcls, float* __restrict__ out) {
    int t = threadIdx.x;
    if (t < OUTC) {
        float a = 0.f;
        for (int k = 0; k < 2 * HM; k++)
            a = fmaf((float)(gRoSum[k] / P), __ldg(&Wcls[k * OUTC + t]), a);
        out[t] = a;
    }
}

// =====================================================================
extern "C" void kernel_launch(void* const* d_in, const int* in_sizes, int n_in,
                              void* d_out, int out_size) {
    const float* patch_feats = (const float*)d_in[0];
    const int*   patch_src   = (const int*)d_in[1];
    const int*   patch_dst   = (const int*)d_in[2];
    const float* patch_ew    = (const float*)d_in[3];
    const int*   mesh_src    = (const int*)d_in[4];
    const int*   mesh_dst    = (const int*)d_in[5];
    const float* mesh_ew     = (const float*)d_in[6];
    const float* W1  = (const float*)d_in[7];
    const float* g1  = (const float*)d_in[8];
    const float* b1  = (const float*)d_in[9];
    const float* W2  = (const float*)d_in[10];
    const float* g2  = (const float*)d_in[11];
    const float* b2  = (const float*)d_in[12];
    const float* We  = (const float*)d_in[13];
    const float* Wc1 = (const float*)d_in[14];
    const float* g3  = (const float*)d_in[15];
    const float* b3  = (const float*)d_in[16];
    const float* Wc2 = (const float*)d_in[17];
    const float* g4  = (const float*)d_in[18];
    const float* b4  = (const float*)d_in[19];
    const float* Wcls = (const float*)d_in[20];
    float* out = (float*)d_out;

    cudaFuncSetAttribute(patch_kernel, cudaFuncAttributeMaxDynamicSharedMemorySize, SMEM_PATCH);

    void *pEmb, *pAgg1, *pAgg2, *pH, *pH2;
    cudaGetSymbolAddress(&pEmb,  gEmb);
    cudaGetSymbolAddress(&pAgg1, gAgg1);
    cudaGetSymbolAddress(&pAgg2, gAgg2);
    cudaGetSymbolAddress(&pH,    gH);
    cudaGetSymbolAddress(&pH2,   gH2);

    // keep patch_kernel as 4th launch so ncu's window lands on it
    init_zero<<<(P + 255) / 256, 256>>>();
    mesh_deg<<<(EM + 255) / 256, 256>>>(mesh_src, mesh_dst);
    mesh_rs<<<(P + 255) / 256, 256>>>();

    patch_kernel<<<P, TPB, SMEM_PATCH>>>(patch_feats, patch_src, patch_dst, patch_ew,
                                         W1, g1, b1, W2, g2, b2, We);

    mesh_scan<<<1, 256>>>();
    mesh_sort<<<(EM + 255) / 256, 256>>>(mesh_src, mesh_dst, mesh_ew);

    // mesh conv1
    mesh_gather128<<<P / 8, 256>>>((const float*)pEmb, (float*)pAgg1);
    mesh_gemm<RD><<<P / 16, 256>>>((const float*)pAgg1, Wc1, (float*)pH);
    mesh_stats<<<P / 50, 256>>>((const float*)pH, 0);
    mesh_finalize<<<1, 256>>>(g3, b3, 0);
    mesh_apply<<<P / 50, 256>>>((float*)pH, 0);

    // mesh conv2
    mesh_gather256<<<P / 4, 256>>>((const float*)pH, (float*)pAgg2);
    mesh_gemm<HM><<<P / 16, 256>>>((const float*)pAgg2, Wc2, (float*)pH2);
    mesh_stats<<<P / 50, 256>>>((const float*)pH2, HM);
    mesh_finalize<<<1, 256>>>(g4, b4, HM);
    mesh_apply<<<P / 50, 256>>>((float*)pH2, HM);

    final_kernel<<<1, 32>>>(Wcls, out);
}